// round 1
// baseline (speedup 1.0000x reference)
#include <cuda_runtime.h>
#include <math.h>

// ---------------------------------------------------------------------------
// Problem constants
// ---------------------------------------------------------------------------
#define CB   8          // batch
#define CN   2048       // query tokens
#define CD_  512        // model dim
#define CS   256        // context tokens
#define CCD  768        // context dim
#define CH   8          // heads
#define CDH  64         // head dim
#define CINNER 512
#define CFF  2048
#define CBN  (CB*CN)    // 16384
#define CBS  (CB*CS)    // 2048

// ---------------------------------------------------------------------------
// Scratch (static device globals; no allocation allowed)
// ---------------------------------------------------------------------------
__device__ float g_h  [(size_t)CBN * CD_];
__device__ float g_q  [(size_t)CBN * CINNER];
__device__ float g_k  [(size_t)CBN * CINNER];
__device__ float g_v  [(size_t)CBN * CINNER];
__device__ float g_att[(size_t)CBN * CINNER];
__device__ float g_x1 [(size_t)CBN * CD_];
__device__ float g_x2 [(size_t)CBN * CD_];
__device__ float g_p  [(size_t)CBN * 2 * CFF];
__device__ float g_g  [(size_t)CBN * CFF];
__device__ float g_ck [(size_t)CBS * CINNER];
__device__ float g_cv [(size_t)CBS * CINNER];

// ---------------------------------------------------------------------------
// LayerNorm: one block per row (D=512), 128 threads x float4
// ---------------------------------------------------------------------------
__global__ __launch_bounds__(128)
void ln_kernel(const float* __restrict__ in, const float* __restrict__ gamma,
               const float* __restrict__ beta, float* __restrict__ out)
{
    const int row = blockIdx.x;
    const int t   = threadIdx.x;
    const float4* rp = (const float4*)(in + (size_t)row * CD_);
    float4 v = rp[t];

    float s  = v.x + v.y + v.z + v.w;
    float ss = v.x*v.x + v.y*v.y + v.z*v.z + v.w*v.w;
    #pragma unroll
    for (int o = 16; o > 0; o >>= 1) {
        s  += __shfl_xor_sync(0xFFFFFFFFu, s,  o);
        ss += __shfl_xor_sync(0xFFFFFFFFu, ss, o);
    }
    __shared__ float sh[8];
    if ((t & 31) == 0) { sh[t >> 5] = s; sh[4 + (t >> 5)] = ss; }
    __syncthreads();
    s  = sh[0] + sh[1] + sh[2] + sh[3];
    ss = sh[4] + sh[5] + sh[6] + sh[7];

    const float mean = s * (1.0f / CD_);
    const float var  = ss * (1.0f / CD_) - mean * mean;
    const float rstd = rsqrtf(var + 1e-5f);

    float4 gv = ((const float4*)gamma)[t];
    float4 bv = ((const float4*)beta)[t];
    float4 o;
    o.x = (v.x - mean) * rstd * gv.x + bv.x;
    o.y = (v.y - mean) * rstd * gv.y + bv.y;
    o.z = (v.z - mean) * rstd * gv.z + bv.z;
    o.w = (v.w - mean) * rstd * gv.w + bv.w;
    ((float4*)(out + (size_t)row * CD_))[t] = o;
}

// ---------------------------------------------------------------------------
// Tiled SGEMM:  C[M,Nc] = A[M,K] @ W[K,Nc] (+bias) (+res) (optionally masked)
// BM=BN=64, BK=16, 256 threads, 4x4 micro-tile.
// Requires M%64==0, Nc%64==0, K%16==0 (true for all shapes here).
// If lengths != nullptr, rows are interpreted as b*2048+n and masked rows -> 0.
// ---------------------------------------------------------------------------
__global__ __launch_bounds__(256)
void gemm_kernel(const float* __restrict__ A, const float* __restrict__ W,
                 const float* __restrict__ bias, const float* __restrict__ res,
                 float* __restrict__ C, int M, int Nc, int K,
                 const int* __restrict__ lengths)
{
    __shared__ float As[16][64];
    __shared__ float Bs[16][64];

    const int tid  = threadIdx.x;
    const int tx   = tid & 15;
    const int ty   = tid >> 4;
    const int aRow = tid >> 2;       // 0..63
    const int aC4  = tid & 3;        // 0..3   (4 float4 along K)
    const int bRow = tid >> 4;       // 0..15
    const int bC4  = tid & 15;       // 0..15  (16 float4 along Nc)

    const int rowBase = blockIdx.y * 64;
    const int colBase = blockIdx.x * 64;

    float acc[4][4];
    #pragma unroll
    for (int i = 0; i < 4; i++)
        #pragma unroll
        for (int j = 0; j < 4; j++) acc[i][j] = 0.0f;

    for (int k0 = 0; k0 < K; k0 += 16) {
        float4 a = *(const float4*)(A + (size_t)(rowBase + aRow) * K + k0 + aC4 * 4);
        As[aC4 * 4 + 0][aRow] = a.x;
        As[aC4 * 4 + 1][aRow] = a.y;
        As[aC4 * 4 + 2][aRow] = a.z;
        As[aC4 * 4 + 3][aRow] = a.w;
        *(float4*)&Bs[bRow][bC4 * 4] =
            *(const float4*)(W + (size_t)(k0 + bRow) * Nc + colBase + bC4 * 4);
        __syncthreads();

        #pragma unroll
        for (int kk = 0; kk < 16; kk++) {
            float4 av = *(const float4*)&As[kk][ty * 4];
            float4 bv = *(const float4*)&Bs[kk][tx * 4];
            float ar[4] = {av.x, av.y, av.z, av.w};
            float br[4] = {bv.x, bv.y, bv.z, bv.w};
            #pragma unroll
            for (int i = 0; i < 4; i++)
                #pragma unroll
                for (int j = 0; j < 4; j++)
                    acc[i][j] += ar[i] * br[j];
        }
        __syncthreads();
    }

    #pragma unroll
    for (int i = 0; i < 4; i++) {
        const int row = rowBase + ty * 4 + i;
        bool zero = false;
        if (lengths) {
            const int b = row >> 11;      // row / 2048
            const int n = row & 2047;
            zero = (n >= lengths[b]);
        }
        const int col = colBase + tx * 4;
        float4 o;
        float vv[4];
        #pragma unroll
        for (int j = 0; j < 4; j++) {
            float val = acc[i][j];
            if (bias) val += bias[col + j];
            if (res)  val += res[(size_t)row * Nc + col + j];
            vv[j] = zero ? 0.0f : val;
        }
        o.x = vv[0]; o.y = vv[1]; o.z = vv[2]; o.w = vv[3];
        *(float4*)(C + (size_t)row * Nc + col) = o;
    }
}

// ---------------------------------------------------------------------------
// Flash attention (fp32): 1 thread = 1 query row, 64-key K/V smem tiles,
// online softmax with rare-rescale. Q layout [B*2048, 512], head h at cols
// h*64..h*64+63. kv_len is 2048 (self) or 256 (cross); multiple of 64.
// ---------------------------------------------------------------------------
__global__ __launch_bounds__(128)
void attn_kernel(const float* __restrict__ Q, const float* __restrict__ K,
                 const float* __restrict__ V, const int* __restrict__ lengths,
                 float* __restrict__ O, int kv_len)
{
    const int b = blockIdx.z;
    const int h = blockIdx.y;
    const int qrow = b * CN + blockIdx.x * 128 + threadIdx.x;

    float q[64];
    {
        const float4* qp = (const float4*)(Q + (size_t)qrow * CINNER + h * CDH);
        #pragma unroll
        for (int d4 = 0; d4 < 16; d4++) {
            float4 t4 = qp[d4];
            q[4*d4+0] = t4.x * 0.125f;
            q[4*d4+1] = t4.y * 0.125f;
            q[4*d4+2] = t4.z * 0.125f;
            q[4*d4+3] = t4.w * 0.125f;
        }
    }

    float m = -1e30f, l = 0.0f;
    float acc[64];
    #pragma unroll
    for (int d = 0; d < 64; d++) acc[d] = 0.0f;

    const int valid = lengths ? lengths[b] : kv_len;
    const size_t kvBase = (size_t)b * kv_len;

    __shared__ float Ks[64][64];
    __shared__ float Vs[64][64];

    for (int t0 = 0; t0 < valid; t0 += 64) {
        const int tcount = min(64, valid - t0);
        // load 64x64 tiles (full tile always in-bounds: kv_len % 64 == 0)
        for (int i = threadIdx.x; i < 64 * 16; i += 128) {
            const int r  = i >> 4;
            const int c4 = i & 15;
            const size_t src = (kvBase + t0 + r) * CINNER + h * CDH + c4 * 4;
            ((float4*)Ks[r])[c4] = *(const float4*)(K + src);
            ((float4*)Vs[r])[c4] = *(const float4*)(V + src);
        }
        __syncthreads();

        for (int j = 0; j < tcount; j++) {
            const float4* kr = (const float4*)Ks[j];
            float s = 0.0f;
            #pragma unroll
            for (int d4 = 0; d4 < 16; d4++) {
                float4 kk = kr[d4];
                s += q[4*d4+0]*kk.x + q[4*d4+1]*kk.y
                   + q[4*d4+2]*kk.z + q[4*d4+3]*kk.w;
            }
            if (s > m) {
                const float c = __expf(m - s);
                l *= c;
                #pragma unroll
                for (int d = 0; d < 64; d++) acc[d] *= c;
                m = s;
            }
            const float pr = __expf(s - m);
            l += pr;
            const float4* vr = (const float4*)Vs[j];
            #pragma unroll
            for (int d4 = 0; d4 < 16; d4++) {
                float4 vv = vr[d4];
                acc[4*d4+0] += pr * vv.x;
                acc[4*d4+1] += pr * vv.y;
                acc[4*d4+2] += pr * vv.z;
                acc[4*d4+3] += pr * vv.w;
            }
        }
        __syncthreads();
    }

    const float inv = 1.0f / l;
    float4* op = (float4*)(O + (size_t)qrow * CINNER + h * CDH);
    #pragma unroll
    for (int d4 = 0; d4 < 16; d4++) {
        float4 o;
        o.x = acc[4*d4+0] * inv;
        o.y = acc[4*d4+1] * inv;
        o.z = acc[4*d4+2] * inv;
        o.w = acc[4*d4+3] * inv;
        op[d4] = o;
    }
}

// ---------------------------------------------------------------------------
// GEGLU: out[row,c] = p[row,c] * gelu_exact(p[row, 2048+c]),  c in [0,2048)
// ---------------------------------------------------------------------------
__global__ __launch_bounds__(256)
void geglu_kernel(const float* __restrict__ p, float* __restrict__ out)
{
    const size_t i = (size_t)blockIdx.x * 256 + threadIdx.x;
    const size_t row = i >> 11;          // / 2048
    const size_t col = i & 2047;
    const float a = p[row * (2 * CFF) + col];
    const float g = p[row * (2 * CFF) + CFF + col];
    const float gelu = 0.5f * g * (1.0f + erff(g * 0.70710678118654752f));
    out[i] = a * gelu;
}

// ---------------------------------------------------------------------------
// Launch
// ---------------------------------------------------------------------------
extern "C" void kernel_launch(void* const* d_in, const int* in_sizes, int n_in,
                              void* d_out, int out_size)
{
    (void)in_sizes; (void)n_in; (void)out_size;
    const float* x      = (const float*)d_in[0];
    const float* ctx    = (const float*)d_in[1];
    const int*   len    = (const int*)  d_in[2];
    const float* wq1    = (const float*)d_in[3];
    const float* wk1    = (const float*)d_in[4];
    const float* wv1    = (const float*)d_in[5];
    const float* wo1    = (const float*)d_in[6];
    const float* bo1    = (const float*)d_in[7];
    const float* wq2    = (const float*)d_in[8];
    const float* wk2    = (const float*)d_in[9];
    const float* wv2    = (const float*)d_in[10];
    const float* wo2    = (const float*)d_in[11];
    const float* bo2    = (const float*)d_in[12];
    const float* wff_in = (const float*)d_in[13];
    const float* bff_in = (const float*)d_in[14];
    const float* wff_out= (const float*)d_in[15];
    const float* bff_out= (const float*)d_in[16];
    const float* g1     = (const float*)d_in[17];
    const float* b1     = (const float*)d_in[18];
    const float* g2     = (const float*)d_in[19];
    const float* b2     = (const float*)d_in[20];
    const float* g3     = (const float*)d_in[21];
    const float* b3     = (const float*)d_in[22];
    float* out = (float*)d_out;

    float *h, *q, *k, *v, *att, *x1, *x2, *p, *gg, *ck, *cv;
    cudaGetSymbolAddress((void**)&h,  g_h);
    cudaGetSymbolAddress((void**)&q,  g_q);
    cudaGetSymbolAddress((void**)&k,  g_k);
    cudaGetSymbolAddress((void**)&v,  g_v);
    cudaGetSymbolAddress((void**)&att,g_att);
    cudaGetSymbolAddress((void**)&x1, g_x1);
    cudaGetSymbolAddress((void**)&x2, g_x2);
    cudaGetSymbolAddress((void**)&p,  g_p);
    cudaGetSymbolAddress((void**)&gg, g_g);
    cudaGetSymbolAddress((void**)&ck, g_ck);
    cudaGetSymbolAddress((void**)&cv, g_cv);

    const dim3 gProj(512 / 64, CBN / 64);     // [16384,512] x [512/768/2048,512]
    const dim3 gCtx (512 / 64, CBS / 64);     // [2048,512]
    const dim3 gFFin(4096 / 64, CBN / 64);    // [16384,4096]
    const dim3 gAttn(CN / 128, CH, CB);

    // ---- Phase 1: self-attention ----
    ln_kernel<<<CBN, 128>>>(x, g1, b1, h);
    gemm_kernel<<<gProj, 256>>>(h, wq1, nullptr, nullptr, q,  CBN, 512, 512, nullptr);
    gemm_kernel<<<gProj, 256>>>(h, wk1, nullptr, nullptr, k,  CBN, 512, 512, nullptr);
    gemm_kernel<<<gProj, 256>>>(h, wv1, nullptr, nullptr, v,  CBN, 512, 512, nullptr);
    attn_kernel<<<gAttn, 128>>>(q, k, v, len, att, CN);
    gemm_kernel<<<gProj, 256>>>(att, wo1, bo1, x, x1, CBN, 512, 512, nullptr);

    // ---- Phase 2: cross-attention ----
    ln_kernel<<<CBN, 128>>>(x1, g2, b2, h);
    gemm_kernel<<<gProj, 256>>>(h, wq2, nullptr, nullptr, q, CBN, 512, 512, nullptr);
    gemm_kernel<<<gCtx, 256>>>(ctx, wk2, nullptr, nullptr, ck, CBS, 512, 768, nullptr);
    gemm_kernel<<<gCtx, 256>>>(ctx, wv2, nullptr, nullptr, cv, CBS, 512, 768, nullptr);
    attn_kernel<<<gAttn, 128>>>(q, ck, cv, nullptr, att, CS);
    gemm_kernel<<<gProj, 256>>>(att, wo2, bo2, x1, x2, CBN, 512, 512, nullptr);

    // ---- Phase 3: GEGLU feed-forward (+ final token mask fused in epilogue) ----
    ln_kernel<<<CBN, 128>>>(x2, g3, b3, h);
    gemm_kernel<<<gFFin, 256>>>(h, wff_in, bff_in, nullptr, p, CBN, 4096, 512, nullptr);
    geglu_kernel<<<((size_t)CBN * CFF) / 256, 256>>>(p, gg);
    gemm_kernel<<<gProj, 256>>>(gg, wff_out, bff_out, x2, out, CBN, 512, 2048, len);
}

// round 6
// speedup vs baseline: 1.1789x; 1.1789x over previous
#include <cuda.h>
#include <cuda_runtime.h>
#include <cuda_bf16.h>
#include <math.h>
#include <stdint.h>

// ---------------------------------------------------------------------------
// Problem constants
// ---------------------------------------------------------------------------
#define CB   8
#define CN   2048
#define CD_  512
#define CS   256
#define CCD  768
#define CH   8
#define CDH  64
#define CINNER 512
#define CFF  2048
#define CBN  (CB*CN)    // 16384
#define CBS  (CB*CS)    // 2048

// ---------------------------------------------------------------------------
// PTX helpers — family-safe only
// ---------------------------------------------------------------------------
__device__ __forceinline__ void cpa16(uint32_t dst, const void* src) {
    asm volatile("cp.async.ca.shared.global [%0], [%1], 16;" :: "r"(dst), "l"(src));
}
#define CP_COMMIT() asm volatile("cp.async.commit_group;" ::: "memory")
#define CP_WAIT(n)  asm volatile("cp.async.wait_group %0;" :: "n"(n) : "memory")

__device__ __forceinline__ uint32_t smem_u32(const void* p) {
    uint32_t a;
    asm("{ .reg .u64 t; cvta.to.shared.u64 t, %1; cvt.u32.u64 %0, t; }"
        : "=r"(a) : "l"(p));
    return a;
}

__device__ __forceinline__ void mma_bf16(float* c, const uint32_t* a, const uint32_t* b) {
    asm volatile("mma.sync.aligned.m16n8k16.row.col.f32.bf16.bf16.f32 "
                 "{%0,%1,%2,%3}, {%4,%5,%6,%7}, {%8,%9}, {%0,%1,%2,%3};"
                 : "+f"(c[0]), "+f"(c[1]), "+f"(c[2]), "+f"(c[3])
                 : "r"(a[0]), "r"(a[1]), "r"(a[2]), "r"(a[3]), "r"(b[0]), "r"(b[1]));
}

// ---------------------------------------------------------------------------
// Scratch (static device globals)
// ---------------------------------------------------------------------------
__device__ float g_h  [(size_t)CBN * CD_];
__device__ float g_att[(size_t)CBN * CINNER];
__device__ float g_gg [(size_t)CBN * CFF];
__device__ float g_qkv[(size_t)CBN * 1536];
__device__ float g_q2 [(size_t)CBN * 512];
__device__ float g_ckv[(size_t)CBS * 1024];
__device__ float g_x1 [(size_t)CBN * 512];
__device__ float g_x2 [(size_t)CBN * 512];
__device__ float g_p  [(size_t)CBN * 4096];
__device__ float g_wfit[4096 * 512];   // wff_in transposed [N,K] for HMMA

// ---------------------------------------------------------------------------
// Weight transpose (fp32): W[K,N] -> out[N,K].  block (32,8), grid (N/32,K/32)
// ---------------------------------------------------------------------------
__global__ __launch_bounds__(256)
void transp32(const float* __restrict__ W, int K, int N,
              float* __restrict__ o, int rowOff)
{
    __shared__ float t[32][33];
    const int k0 = blockIdx.y * 32, n0 = blockIdx.x * 32;
    const int tx = threadIdx.x, ty = threadIdx.y;
    #pragma unroll
    for (int i = 0; i < 4; i++)
        t[ty + i * 8][tx] = W[(size_t)(k0 + ty + i * 8) * N + n0 + tx];
    __syncthreads();
    #pragma unroll
    for (int i = 0; i < 4; i++) {
        const int n = n0 + ty + i * 8, k = k0 + tx;
        o[(size_t)(rowOff + n) * K + k] = t[tx][ty + i * 8];
    }
}

// ---------------------------------------------------------------------------
// LayerNorm (fp32). One block per row (D=512), 128 threads x float4. [R1-proven]
// ---------------------------------------------------------------------------
__global__ __launch_bounds__(128)
void ln_kernel(const float* __restrict__ in, const float* __restrict__ gamma,
               const float* __restrict__ beta, float* __restrict__ out)
{
    const int row = blockIdx.x;
    const int t   = threadIdx.x;
    const float4 v = ((const float4*)(in + (size_t)row * CD_))[t];

    float s  = v.x + v.y + v.z + v.w;
    float ss = v.x*v.x + v.y*v.y + v.z*v.z + v.w*v.w;
    #pragma unroll
    for (int o = 16; o > 0; o >>= 1) {
        s  += __shfl_xor_sync(0xFFFFFFFFu, s,  o);
        ss += __shfl_xor_sync(0xFFFFFFFFu, ss, o);
    }
    __shared__ float sh[8];
    if ((t & 31) == 0) { sh[t >> 5] = s; sh[4 + (t >> 5)] = ss; }
    __syncthreads();
    s  = sh[0] + sh[1] + sh[2] + sh[3];
    ss = sh[4] + sh[5] + sh[6] + sh[7];

    const float mean = s * (1.0f / CD_);
    const float rstd = rsqrtf(ss * (1.0f / CD_) - mean * mean + 1e-5f);

    const float4 gv = ((const float4*)gamma)[t];
    const float4 bv = ((const float4*)beta)[t];
    float4 o;
    o.x = (v.x - mean) * rstd * gv.x + bv.x;
    o.y = (v.y - mean) * rstd * gv.y + bv.y;
    o.z = (v.z - mean) * rstd * gv.z + bv.z;
    o.w = (v.w - mean) * rstd * gv.w + bv.w;
    ((float4*)(out + (size_t)row * CD_))[t] = o;
}

// ---------------------------------------------------------------------------
// R1-PROVEN fp32 SGEMM (verbatim core) + Cld/colOff extension for fused slices.
//   C[row*Cld + colOff + col] = A[M,K] @ W[K,Nc] (+bias)(+res)(mask)
// BM=BN=64, BK=16, 256 threads, 4x4 micro-tile. res only valid when colOff=0
// and res stride == Cld.
// ---------------------------------------------------------------------------
__global__ __launch_bounds__(256)
void gemm32(const float* __restrict__ A, const float* __restrict__ W,
            const float* __restrict__ bias, const float* __restrict__ res,
            float* __restrict__ C, int M, int Nc, int K,
            int Cld, int colOff, const int* __restrict__ lengths)
{
    __shared__ float As[16][64];
    __shared__ float Bs[16][64];

    const int tid  = threadIdx.x;
    const int tx   = tid & 15;
    const int ty   = tid >> 4;
    const int aRow = tid >> 2;
    const int aC4  = tid & 3;
    const int bRow = tid >> 4;
    const int bC4  = tid & 15;

    const int rowBase = blockIdx.y * 64;
    const int colBase = blockIdx.x * 64;

    float acc[4][4];
    #pragma unroll
    for (int i = 0; i < 4; i++)
        #pragma unroll
        for (int j = 0; j < 4; j++) acc[i][j] = 0.0f;

    for (int k0 = 0; k0 < K; k0 += 16) {
        float4 a = *(const float4*)(A + (size_t)(rowBase + aRow) * K + k0 + aC4 * 4);
        As[aC4 * 4 + 0][aRow] = a.x;
        As[aC4 * 4 + 1][aRow] = a.y;
        As[aC4 * 4 + 2][aRow] = a.z;
        As[aC4 * 4 + 3][aRow] = a.w;
        *(float4*)&Bs[bRow][bC4 * 4] =
            *(const float4*)(W + (size_t)(k0 + bRow) * Nc + colBase + bC4 * 4);
        __syncthreads();

        #pragma unroll
        for (int kk = 0; kk < 16; kk++) {
            float4 av = *(const float4*)&As[kk][ty * 4];
            float4 bv = *(const float4*)&Bs[kk][tx * 4];
            float ar[4] = {av.x, av.y, av.z, av.w};
            float br[4] = {bv.x, bv.y, bv.z, bv.w};
            #pragma unroll
            for (int i = 0; i < 4; i++)
                #pragma unroll
                for (int j = 0; j < 4; j++)
                    acc[i][j] += ar[i] * br[j];
        }
        __syncthreads();
    }

    #pragma unroll
    for (int i = 0; i < 4; i++) {
        const int row = rowBase + ty * 4 + i;
        bool zero = false;
        if (lengths) {
            const int b = row >> 11;
            const int n = row & 2047;
            zero = (n >= lengths[b]);
        }
        const int col = colBase + tx * 4;
        float vv[4];
        #pragma unroll
        for (int j = 0; j < 4; j++) {
            float val = acc[i][j];
            if (bias) val += bias[col + j];
            if (res)  val += res[(size_t)row * Cld + col + j];
            vv[j] = zero ? 0.0f : val;
        }
        float4 o;
        o.x = vv[0]; o.y = vv[1]; o.z = vv[2]; o.w = vv[3];
        *(float4*)(C + (size_t)row * Cld + colOff + col) = o;
    }
}

// ---------------------------------------------------------------------------
// HMMA bf16x4 GEMM with in-kernel truncation hi/lo split (R5 kernel, used for
// FF-in only this round):  C[M,Nc] = A[M,K] @ B^T (+bias), B stored [N,K].
// ---------------------------------------------------------------------------
#define T_AHI 0
#define T_ALO 10240
#define T_BHI 20480
#define T_BLO 30720
#define STG_OFF 40960
#define STG_SZ  32768
#define GSMEMT (STG_OFF + 2 * STG_SZ)

__global__ __launch_bounds__(256, 2)
void gemm_mma32(const float* __restrict__ A, const float* __restrict__ B,
                const float* __restrict__ bias, const float* __restrict__ res,
                float* __restrict__ C, int M, int Nc, int K,
                const int* __restrict__ lengths)
{
    extern __shared__ __align__(1024) char smem_raw[];
    const uint32_t sb = smem_u32(smem_raw);
    const int tid = threadIdx.x;
    const int wid = tid >> 5, l = tid & 31;
    const int wm = (wid >> 2) * 64;
    const int wn = (wid & 3) * 32;
    const int g  = l >> 2;
    const int qd = (l & 3) * 2;

    const int rowBase = blockIdx.y * 128;
    const int colBase = blockIdx.x * 128;

    const int seg = tid & 7;
    const int rb  = tid >> 3;

    float acc[4][4][4];
    #pragma unroll
    for (int a = 0; a < 4; a++)
        #pragma unroll
        for (int b = 0; b < 4; b++)
            #pragma unroll
            for (int c = 0; c < 4; c++) acc[a][b][c] = 0.0f;

    const int nch = K >> 5;

    #pragma unroll
    for (int it = 0; it < 8; it++) {
        const int grow = rb + it * 32;
        const float* src = (it < 4) ? (A + (size_t)(rowBase + grow) * K)
                                    : (B + (size_t)(colBase + grow - 128) * K);
        cpa16(sb + STG_OFF + (uint32_t)(grow * 128 + seg * 16), src + seg * 4);
    }
    CP_COMMIT();

    for (int ck = 0; ck < nch; ck++) {
        if (ck + 1 < nch) {
            const int kb = (ck + 1) * 32;
            const uint32_t ds = sb + STG_OFF + (uint32_t)(((ck + 1) & 1) * STG_SZ);
            #pragma unroll
            for (int it = 0; it < 8; it++) {
                const int grow = rb + it * 32;
                const float* src = (it < 4) ? (A + (size_t)(rowBase + grow) * K)
                                            : (B + (size_t)(colBase + grow - 128) * K);
                cpa16(ds + (uint32_t)(grow * 128 + seg * 16), src + kb + seg * 4);
            }
            CP_COMMIT();
            CP_WAIT(1);
        } else {
            CP_WAIT(0);
        }
        __syncthreads();

        {
            const char* sp = smem_raw + STG_OFF + (size_t)(ck & 1) * STG_SZ;
            #pragma unroll
            for (int it = 0; it < 8; it++) {
                const int grow = rb + it * 32;
                const float4 v = *(const float4*)(sp + grow * 128 + seg * 16);
                const uint32_t u0 = __float_as_uint(v.x), u1 = __float_as_uint(v.y);
                const uint32_t u2 = __float_as_uint(v.z), u3 = __float_as_uint(v.w);
                const uint32_t hi0 = (u0 >> 16) | (u1 & 0xFFFF0000u);
                const uint32_t hi1 = (u2 >> 16) | (u3 & 0xFFFF0000u);
                const float l0 = v.x - __uint_as_float(u0 & 0xFFFF0000u);
                const float l1 = v.y - __uint_as_float(u1 & 0xFFFF0000u);
                const float l2 = v.z - __uint_as_float(u2 & 0xFFFF0000u);
                const float l3 = v.w - __uint_as_float(u3 & 0xFFFF0000u);
                __nv_bfloat162 lp0 = __floats2bfloat162_rn(l0, l1);
                __nv_bfloat162 lp1 = __floats2bfloat162_rn(l2, l3);
                const uint32_t lo0 = *reinterpret_cast<uint32_t*>(&lp0);
                const uint32_t lo1 = *reinterpret_cast<uint32_t*>(&lp1);
                const int tr = grow & 127;
                char* hb = smem_raw + ((it < 4) ? T_AHI : T_BHI) + tr * 80 + seg * 8;
                char* lb = smem_raw + ((it < 4) ? T_ALO : T_BLO) + tr * 80 + seg * 8;
                *(uint2*)hb = make_uint2(hi0, hi1);
                *(uint2*)lb = make_uint2(lo0, lo1);
            }
        }
        __syncthreads();

        #pragma unroll
        for (int s = 0; s < 32; s += 16) {
            const int c0 = (s + qd) * 2;
            const int c1 = (s + qd + 8) * 2;
            uint32_t a[4][4], bh[4][2], bl[4][2];

            #pragma unroll
            for (int nt = 0; nt < 4; nt++) {
                const int ro = (wn + nt * 8 + g) * 80;
                bh[nt][0] = *(const uint32_t*)(smem_raw + T_BHI + ro + c0);
                bh[nt][1] = *(const uint32_t*)(smem_raw + T_BHI + ro + c1);
                bl[nt][0] = *(const uint32_t*)(smem_raw + T_BLO + ro + c0);
                bl[nt][1] = *(const uint32_t*)(smem_raw + T_BLO + ro + c1);
            }
            #pragma unroll
            for (int mt = 0; mt < 4; mt++) {
                const int r0 = (wm + mt * 16 + g) * 80;
                const int r1 = r0 + 8 * 80;
                a[mt][0] = *(const uint32_t*)(smem_raw + T_AHI + r0 + c0);
                a[mt][1] = *(const uint32_t*)(smem_raw + T_AHI + r1 + c0);
                a[mt][2] = *(const uint32_t*)(smem_raw + T_AHI + r0 + c1);
                a[mt][3] = *(const uint32_t*)(smem_raw + T_AHI + r1 + c1);
            }
            #pragma unroll
            for (int mt = 0; mt < 4; mt++)
                #pragma unroll
                for (int nt = 0; nt < 4; nt++)
                    mma_bf16(acc[mt][nt], a[mt], bh[nt]);
            #pragma unroll
            for (int mt = 0; mt < 4; mt++)
                #pragma unroll
                for (int nt = 0; nt < 4; nt++)
                    mma_bf16(acc[mt][nt], a[mt], bl[nt]);
            #pragma unroll
            for (int mt = 0; mt < 4; mt++) {
                const int r0 = (wm + mt * 16 + g) * 80;
                const int r1 = r0 + 8 * 80;
                a[mt][0] = *(const uint32_t*)(smem_raw + T_ALO + r0 + c0);
                a[mt][1] = *(const uint32_t*)(smem_raw + T_ALO + r1 + c0);
                a[mt][2] = *(const uint32_t*)(smem_raw + T_ALO + r0 + c1);
                a[mt][3] = *(const uint32_t*)(smem_raw + T_ALO + r1 + c1);
            }
            #pragma unroll
            for (int mt = 0; mt < 4; mt++)
                #pragma unroll
                for (int nt = 0; nt < 4; nt++)
                    mma_bf16(acc[mt][nt], a[mt], bh[nt]);
            #pragma unroll
            for (int mt = 0; mt < 4; mt++)
                #pragma unroll
                for (int nt = 0; nt < 4; nt++)
                    mma_bf16(acc[mt][nt], a[mt], bl[nt]);
        }
    }

    #pragma unroll
    for (int mt = 0; mt < 4; mt++) {
        #pragma unroll
        for (int hrow = 0; hrow < 2; hrow++) {
            const int row = rowBase + wm + mt * 16 + g + hrow * 8;
            bool zero = false;
            if (lengths) zero = ((row & 2047) >= lengths[row >> 11]);
            #pragma unroll
            for (int nt = 0; nt < 4; nt++) {
                const int col = colBase + wn + nt * 8 + qd;
                float v0 = acc[mt][nt][hrow * 2 + 0];
                float v1 = acc[mt][nt][hrow * 2 + 1];
                if (bias) { v0 += bias[col]; v1 += bias[col + 1]; }
                if (res) {
                    const float2 rr = *(const float2*)(res + (size_t)row * Nc + col);
                    v0 += rr.x; v1 += rr.y;
                }
                if (zero) { v0 = 0.0f; v1 = 0.0f; }
                *(float2*)(C + (size_t)row * Nc + col) = make_float2(v0, v1);
            }
        }
    }
}

// ---------------------------------------------------------------------------
// Flash attention (fp32, R1-proven core). 1 thread = 1 query row.
// ---------------------------------------------------------------------------
__global__ __launch_bounds__(128)
void attn_kernel(const float* __restrict__ Q, int qStr,
                 const float* __restrict__ KV, int kvStr, int kOff, int vOff,
                 const int* __restrict__ lengths,
                 float* __restrict__ O, int kv_len)
{
    const int b = blockIdx.z;
    const int h = blockIdx.y;
    const int qrow = b * CN + blockIdx.x * 128 + threadIdx.x;

    float q[64];
    {
        const float4* qp = (const float4*)(Q + (size_t)qrow * qStr + h * CDH);
        #pragma unroll
        for (int d4 = 0; d4 < 16; d4++) {
            float4 t4 = qp[d4];
            q[4*d4+0] = t4.x * 0.125f; q[4*d4+1] = t4.y * 0.125f;
            q[4*d4+2] = t4.z * 0.125f; q[4*d4+3] = t4.w * 0.125f;
        }
    }

    float m = -1e30f, l = 0.0f;
    float acc[64];
    #pragma unroll
    for (int d = 0; d < 64; d++) acc[d] = 0.0f;

    const int valid = lengths ? lengths[b] : kv_len;
    const size_t kvBase = (size_t)b * kv_len;

    __shared__ float Ks[64][64];
    __shared__ float Vs[64][64];

    for (int t0 = 0; t0 < valid; t0 += 64) {
        const int tcount = min(64, valid - t0);
        for (int i = threadIdx.x; i < 64 * 16; i += 128) {
            const int r  = i >> 4;
            const int c4 = i & 15;
            const size_t base = (kvBase + t0 + r) * kvStr + h * CDH + c4 * 4;
            ((float4*)Ks[r])[c4] = *(const float4*)(KV + base + kOff);
            ((float4*)Vs[r])[c4] = *(const float4*)(KV + base + vOff);
        }
        __syncthreads();

        for (int j = 0; j < tcount; j++) {
            const float4* kr = (const float4*)Ks[j];
            float s = 0.0f;
            #pragma unroll
            for (int d4 = 0; d4 < 16; d4++) {
                float4 kk = kr[d4];
                s += q[4*d4+0]*kk.x + q[4*d4+1]*kk.y + q[4*d4+2]*kk.z + q[4*d4+3]*kk.w;
            }
            if (s > m) {
                const float c = __expf(m - s);
                l *= c;
                #pragma unroll
                for (int d = 0; d < 64; d++) acc[d] *= c;
                m = s;
            }
            const float pr = __expf(s - m);
            l += pr;
            const float4* vr = (const float4*)Vs[j];
            #pragma unroll
            for (int d4 = 0; d4 < 16; d4++) {
                float4 vv = vr[d4];
                acc[4*d4+0] += pr * vv.x; acc[4*d4+1] += pr * vv.y;
                acc[4*d4+2] += pr * vv.z; acc[4*d4+3] += pr * vv.w;
            }
        }
        __syncthreads();
    }

    const float inv = 1.0f / l;
    float4* op = (float4*)(O + (size_t)qrow * CINNER + h * CDH);
    #pragma unroll
    for (int d4 = 0; d4 < 16; d4++) {
        float4 o;
        o.x = acc[4*d4+0] * inv; o.y = acc[4*d4+1] * inv;
        o.z = acc[4*d4+2] * inv; o.w = acc[4*d4+3] * inv;
        op[d4] = o;
    }
}

// ---------------------------------------------------------------------------
// GEGLU (fp32, R1-proven)
// ---------------------------------------------------------------------------
__global__ __launch_bounds__(256)
void geglu_kernel(const float* __restrict__ p, float* __restrict__ out)
{
    const size_t i = (size_t)blockIdx.x * 256 + threadIdx.x;
    const size_t row = i >> 11;
    const size_t col = i & 2047;
    const float a = p[row * 4096 + col];
    const float gt = p[row * 4096 + 2048 + col];
    const float gelu = 0.5f * gt * (1.0f + erff(gt * 0.70710678118654752f));
    out[i] = a * gelu;
}

// ---------------------------------------------------------------------------
// Launch
// ---------------------------------------------------------------------------
extern "C" void kernel_launch(void* const* d_in, const int* in_sizes, int n_in,
                              void* d_out, int out_size)
{
    (void)in_sizes; (void)n_in; (void)out_size;
    const float* x      = (const float*)d_in[0];
    const float* ctx    = (const float*)d_in[1];
    const int*   len    = (const int*)  d_in[2];
    const float* wq1    = (const float*)d_in[3];
    const float* wk1    = (const float*)d_in[4];
    const float* wv1    = (const float*)d_in[5];
    const float* wo1    = (const float*)d_in[6];
    const float* bo1    = (const float*)d_in[7];
    const float* wq2    = (const float*)d_in[8];
    const float* wk2    = (const float*)d_in[9];
    const float* wv2    = (const float*)d_in[10];
    const float* wo2    = (const float*)d_in[11];
    const float* bo2    = (const float*)d_in[12];
    const float* wff_in = (const float*)d_in[13];
    const float* bff_in = (const float*)d_in[14];
    const float* wff_out= (const float*)d_in[15];
    const float* bff_out= (const float*)d_in[16];
    const float* g1     = (const float*)d_in[17];
    const float* b1     = (const float*)d_in[18];
    const float* g2     = (const float*)d_in[19];
    const float* b2     = (const float*)d_in[20];
    const float* g3     = (const float*)d_in[21];
    const float* b3     = (const float*)d_in[22];
    float* out = (float*)d_out;

    cudaFuncSetAttribute(gemm_mma32, cudaFuncAttributeMaxDynamicSharedMemorySize, GSMEMT);

    float *h, *att, *gg, *qkv, *q2, *ckv, *x1, *x2, *p, *wfit;
    cudaGetSymbolAddress((void**)&h,   g_h);
    cudaGetSymbolAddress((void**)&att, g_att);
    cudaGetSymbolAddress((void**)&gg,  g_gg);
    cudaGetSymbolAddress((void**)&qkv, g_qkv);
    cudaGetSymbolAddress((void**)&q2,  g_q2);
    cudaGetSymbolAddress((void**)&ckv, g_ckv);
    cudaGetSymbolAddress((void**)&x1,  g_x1);
    cudaGetSymbolAddress((void**)&x2,  g_x2);
    cudaGetSymbolAddress((void**)&p,   g_p);
    cudaGetSymbolAddress((void**)&wfit, g_wfit);

    // ---- weight prep: only wff_in needs transpose (for the HMMA FF-in) ----
    transp32<<<dim3(128, 16), dim3(32, 8)>>>(wff_in, 512, 4096, wfit, 0);

    const dim3 gP(8, 256);     // Nc=512, M=16384
    const dim3 gC(8, 32);      // Nc=512, M=2048

    // ---- Phase 1: self-attention ----
    ln_kernel<<<CBN, 128>>>(x, g1, b1, h);
    gemm32<<<gP, 256>>>(h, wq1, nullptr, nullptr, qkv, CBN, 512, 512, 1536, 0,    nullptr);
    gemm32<<<gP, 256>>>(h, wk1, nullptr, nullptr, qkv, CBN, 512, 512, 1536, 512,  nullptr);
    gemm32<<<gP, 256>>>(h, wv1, nullptr, nullptr, qkv, CBN, 512, 512, 1536, 1024, nullptr);
    attn_kernel<<<dim3(CN/128, CH, CB), 128>>>(qkv, 1536, qkv, 1536, 512, 1024,
        len, att, CN);
    gemm32<<<gP, 256>>>(att, wo1, bo1, x, x1, CBN, 512, 512, 512, 0, nullptr);

    // ---- Phase 2: cross-attention ----
    ln_kernel<<<CBN, 128>>>(x1, g2, b2, h);
    gemm32<<<gP, 256>>>(h, wq2, nullptr, nullptr, q2, CBN, 512, 512, 512, 0, nullptr);
    gemm32<<<gC, 256>>>(ctx, wk2, nullptr, nullptr, ckv, CBS, 512, 768, 1024, 0,   nullptr);
    gemm32<<<gC, 256>>>(ctx, wv2, nullptr, nullptr, ckv, CBS, 512, 768, 1024, 512, nullptr);
    attn_kernel<<<dim3(CN/128, CH, CB), 128>>>(q2, 512, ckv, 1024, 0, 512,
        nullptr, att, CS);
    gemm32<<<gP, 256>>>(att, wo2, bo2, x1, x2, CBN, 512, 512, 512, 0, nullptr);

    // ---- Phase 3: GEGLU feed-forward (FF-in on HMMA bf16x4) ----
    ln_kernel<<<CBN, 128>>>(x2, g3, b3, h);
    gemm_mma32<<<dim3(32, 128), 256, GSMEMT>>>(h, wfit,
        bff_in, nullptr, p, CBN, 4096, 512, nullptr);
    geglu_kernel<<<((size_t)CBN * CFF) / 256, 256>>>(p, gg);
    gemm32<<<gP, 256>>>(gg, wff_out, bff_out, x2, out, CBN, 512, 2048, 512, 0, len);
}

// round 8
// speedup vs baseline: 1.3865x; 1.1761x over previous
#include <cuda.h>
#include <cuda_runtime.h>
#include <cuda_bf16.h>
#include <math.h>
#include <stdint.h>

// ---------------------------------------------------------------------------
// Problem constants
// ---------------------------------------------------------------------------
#define CB   8
#define CN   2048
#define CD_  512
#define CS   256
#define CCD  768
#define CH   8
#define CDH  64
#define CINNER 512
#define CFF  2048
#define CBN  (CB*CN)    // 16384
#define CBS  (CB*CS)    // 2048

// ---------------------------------------------------------------------------
// PTX helpers — family-safe only
// ---------------------------------------------------------------------------
__device__ __forceinline__ void cpa16(uint32_t dst, const void* src) {
    asm volatile("cp.async.ca.shared.global [%0], [%1], 16;" :: "r"(dst), "l"(src));
}
#define CP_COMMIT() asm volatile("cp.async.commit_group;" ::: "memory")
#define CP_WAIT(n)  asm volatile("cp.async.wait_group %0;" :: "n"(n) : "memory")

__device__ __forceinline__ uint32_t smem_u32(const void* p) {
    uint32_t a;
    asm("{ .reg .u64 t; cvta.to.shared.u64 t, %1; cvt.u32.u64 %0, t; }"
        : "=r"(a) : "l"(p));
    return a;
}

__device__ __forceinline__ void mma_bf16(float* c, const uint32_t* a, const uint32_t* b) {
    asm volatile("mma.sync.aligned.m16n8k16.row.col.f32.bf16.bf16.f32 "
                 "{%0,%1,%2,%3}, {%4,%5,%6,%7}, {%8,%9}, {%0,%1,%2,%3};"
                 : "+f"(c[0]), "+f"(c[1]), "+f"(c[2]), "+f"(c[3])
                 : "r"(a[0]), "r"(a[1]), "r"(a[2]), "r"(a[3]), "r"(b[0]), "r"(b[1]));
}

// ---------------------------------------------------------------------------
// Scratch (static device globals)
// ---------------------------------------------------------------------------
__device__ float g_h  [(size_t)CBN * CD_];
__device__ float g_att[(size_t)CBN * CINNER];
__device__ float g_gg [(size_t)CBN * CFF];
__device__ float g_qkv[(size_t)CBN * 1536];   // interleaved [row][q|k|v]
__device__ float g_q2 [(size_t)CBN * 512];
__device__ float g_ckv[(size_t)CBS * 1024];   // interleaved [row][k|v]
__device__ float g_x1 [(size_t)CBN * 512];
__device__ float g_x2 [(size_t)CBN * 512];
__device__ float g_p  [(size_t)CBN * 4096];
// transposed weights [N,K] fp32 (for MMA GEMMs only); others stay [K,N]
__device__ float g_wq1t[512 * 512];
__device__ float g_wk1t[512 * 512];
__device__ float g_wv1t[512 * 512];
__device__ float g_wq2t[512 * 512];
__device__ float g_wk2t[512 * 768];
__device__ float g_wv2t[512 * 768];
__device__ float g_wfit[4096 * 512];

// ---------------------------------------------------------------------------
// Weight transpose (fp32): W[K,N] -> out[N,K].  block (32,8), grid (N/32,K/32)
// ---------------------------------------------------------------------------
__global__ __launch_bounds__(256)
void transp32(const float* __restrict__ W, int K, int N, float* __restrict__ o)
{
    __shared__ float t[32][33];
    const int k0 = blockIdx.y * 32, n0 = blockIdx.x * 32;
    const int tx = threadIdx.x, ty = threadIdx.y;
    #pragma unroll
    for (int i = 0; i < 4; i++)
        t[ty + i * 8][tx] = W[(size_t)(k0 + ty + i * 8) * N + n0 + tx];
    __syncthreads();
    #pragma unroll
    for (int i = 0; i < 4; i++) {
        const int n = n0 + ty + i * 8, k = k0 + tx;
        o[(size_t)n * K + k] = t[tx][ty + i * 8];
    }
}

// ---------------------------------------------------------------------------
// LayerNorm (fp32). [proven]
// ---------------------------------------------------------------------------
__global__ __launch_bounds__(128)
void ln_kernel(const float* __restrict__ in, const float* __restrict__ gamma,
               const float* __restrict__ beta, float* __restrict__ out)
{
    const int row = blockIdx.x;
    const int t   = threadIdx.x;
    const float4 v = ((const float4*)(in + (size_t)row * CD_))[t];

    float s  = v.x + v.y + v.z + v.w;
    float ss = v.x*v.x + v.y*v.y + v.z*v.z + v.w*v.w;
    #pragma unroll
    for (int o = 16; o > 0; o >>= 1) {
        s  += __shfl_xor_sync(0xFFFFFFFFu, s,  o);
        ss += __shfl_xor_sync(0xFFFFFFFFu, ss, o);
    }
    __shared__ float sh[8];
    if ((t & 31) == 0) { sh[t >> 5] = s; sh[4 + (t >> 5)] = ss; }
    __syncthreads();
    s  = sh[0] + sh[1] + sh[2] + sh[3];
    ss = sh[4] + sh[5] + sh[6] + sh[7];

    const float mean = s * (1.0f / CD_);
    const float rstd = rsqrtf(ss * (1.0f / CD_) - mean * mean + 1e-5f);

    const float4 gv = ((const float4*)gamma)[t];
    const float4 bv = ((const float4*)beta)[t];
    float4 o;
    o.x = (v.x - mean) * rstd * gv.x + bv.x;
    o.y = (v.y - mean) * rstd * gv.y + bv.y;
    o.z = (v.z - mean) * rstd * gv.z + bv.z;
    o.w = (v.w - mean) * rstd * gv.w + bv.w;
    ((float4*)(out + (size_t)row * CD_))[t] = o;
}

// ---------------------------------------------------------------------------
// R1-proven fp32 SGEMM + Cld/colOff (R6-validated): C = A@W (+bias)(+res)(mask)
// ---------------------------------------------------------------------------
__global__ __launch_bounds__(256)
void gemm32(const float* __restrict__ A, const float* __restrict__ W,
            const float* __restrict__ bias, const float* __restrict__ res,
            float* __restrict__ C, int M, int Nc, int K,
            int Cld, int colOff, const int* __restrict__ lengths)
{
    __shared__ float As[16][64];
    __shared__ float Bs[16][64];

    const int tid  = threadIdx.x;
    const int tx   = tid & 15;
    const int ty   = tid >> 4;
    const int aRow = tid >> 2;
    const int aC4  = tid & 3;
    const int bRow = tid >> 4;
    const int bC4  = tid & 15;

    const int rowBase = blockIdx.y * 64;
    const int colBase = blockIdx.x * 64;

    float acc[4][4];
    #pragma unroll
    for (int i = 0; i < 4; i++)
        #pragma unroll
        for (int j = 0; j < 4; j++) acc[i][j] = 0.0f;

    for (int k0 = 0; k0 < K; k0 += 16) {
        float4 a = *(const float4*)(A + (size_t)(rowBase + aRow) * K + k0 + aC4 * 4);
        As[aC4 * 4 + 0][aRow] = a.x;
        As[aC4 * 4 + 1][aRow] = a.y;
        As[aC4 * 4 + 2][aRow] = a.z;
        As[aC4 * 4 + 3][aRow] = a.w;
        *(float4*)&Bs[bRow][bC4 * 4] =
            *(const float4*)(W + (size_t)(k0 + bRow) * Nc + colBase + bC4 * 4);
        __syncthreads();

        #pragma unroll
        for (int kk = 0; kk < 16; kk++) {
            float4 av = *(const float4*)&As[kk][ty * 4];
            float4 bv = *(const float4*)&Bs[kk][tx * 4];
            float ar[4] = {av.x, av.y, av.z, av.w};
            float br[4] = {bv.x, bv.y, bv.z, bv.w};
            #pragma unroll
            for (int i = 0; i < 4; i++)
                #pragma unroll
                for (int j = 0; j < 4; j++)
                    acc[i][j] += ar[i] * br[j];
        }
        __syncthreads();
    }

    #pragma unroll
    for (int i = 0; i < 4; i++) {
        const int row = rowBase + ty * 4 + i;
        bool zero = false;
        if (lengths) {
            const int b = row >> 11;
            const int n = row & 2047;
            zero = (n >= lengths[b]);
        }
        const int col = colBase + tx * 4;
        float vv[4];
        #pragma unroll
        for (int j = 0; j < 4; j++) {
            float val = acc[i][j];
            if (bias) val += bias[col + j];
            if (res)  val += res[(size_t)row * Cld + col + j];
            vv[j] = zero ? 0.0f : val;
        }
        float4 o;
        o.x = vv[0]; o.y = vv[1]; o.z = vv[2]; o.w = vv[3];
        *(float4*)(C + (size_t)row * Cld + colOff + col) = o;
    }
}

// ---------------------------------------------------------------------------
// HMMA bf16x3 GEMM with in-kernel truncation hi/lo split [R6-validated core],
// extended with Cld/colOff used ONLY in C/res addressing (Cld=Nc, colOff=0
// reproduces the validated call exactly).
//   C[row*Cld + colOff + col] = A[M,K] @ B^T (+bias)(+res)(mask), B is [N,K].
// ---------------------------------------------------------------------------
#define T_AHI 0
#define T_ALO 10240
#define T_BHI 20480
#define T_BLO 30720
#define STG_OFF 40960
#define STG_SZ  32768
#define GSMEMT (STG_OFF + 2 * STG_SZ)

__global__ __launch_bounds__(256, 2)
void gemm_mma32(const float* __restrict__ A, const float* __restrict__ B,
                const float* __restrict__ bias, const float* __restrict__ res,
                float* __restrict__ C, int M, int Nc, int K,
                int Cld, int colOff, const int* __restrict__ lengths)
{
    extern __shared__ __align__(1024) char smem_raw[];
    const uint32_t sb = smem_u32(smem_raw);
    const int tid = threadIdx.x;
    const int wid = tid >> 5, l = tid & 31;
    const int wm = (wid >> 2) * 64;
    const int wn = (wid & 3) * 32;
    const int g  = l >> 2;
    const int qd = (l & 3) * 2;

    const int rowBase = blockIdx.y * 128;
    const int colBase = blockIdx.x * 128;

    const int seg = tid & 7;
    const int rb  = tid >> 3;

    float acc[4][4][4];
    #pragma unroll
    for (int a = 0; a < 4; a++)
        #pragma unroll
        for (int b = 0; b < 4; b++)
            #pragma unroll
            for (int c = 0; c < 4; c++) acc[a][b][c] = 0.0f;

    const int nch = K >> 5;

    #pragma unroll
    for (int it = 0; it < 8; it++) {
        const int grow = rb + it * 32;
        const float* src = (it < 4) ? (A + (size_t)(rowBase + grow) * K)
                                    : (B + (size_t)(colBase + grow - 128) * K);
        cpa16(sb + STG_OFF + (uint32_t)(grow * 128 + seg * 16), src + seg * 4);
    }
    CP_COMMIT();

    for (int ck = 0; ck < nch; ck++) {
        if (ck + 1 < nch) {
            const int kb = (ck + 1) * 32;
            const uint32_t ds = sb + STG_OFF + (uint32_t)(((ck + 1) & 1) * STG_SZ);
            #pragma unroll
            for (int it = 0; it < 8; it++) {
                const int grow = rb + it * 32;
                const float* src = (it < 4) ? (A + (size_t)(rowBase + grow) * K)
                                            : (B + (size_t)(colBase + grow - 128) * K);
                cpa16(ds + (uint32_t)(grow * 128 + seg * 16), src + kb + seg * 4);
            }
            CP_COMMIT();
            CP_WAIT(1);
        } else {
            CP_WAIT(0);
        }
        __syncthreads();

        {
            const char* sp = smem_raw + STG_OFF + (size_t)(ck & 1) * STG_SZ;
            #pragma unroll
            for (int it = 0; it < 8; it++) {
                const int grow = rb + it * 32;
                const float4 v = *(const float4*)(sp + grow * 128 + seg * 16);
                const uint32_t u0 = __float_as_uint(v.x), u1 = __float_as_uint(v.y);
                const uint32_t u2 = __float_as_uint(v.z), u3 = __float_as_uint(v.w);
                const uint32_t hi0 = (u0 >> 16) | (u1 & 0xFFFF0000u);
                const uint32_t hi1 = (u2 >> 16) | (u3 & 0xFFFF0000u);
                const float l0 = v.x - __uint_as_float(u0 & 0xFFFF0000u);
                const float l1 = v.y - __uint_as_float(u1 & 0xFFFF0000u);
                const float l2 = v.z - __uint_as_float(u2 & 0xFFFF0000u);
                const float l3 = v.w - __uint_as_float(u3 & 0xFFFF0000u);
                __nv_bfloat162 lp0 = __floats2bfloat162_rn(l0, l1);
                __nv_bfloat162 lp1 = __floats2bfloat162_rn(l2, l3);
                const uint32_t lo0 = *reinterpret_cast<uint32_t*>(&lp0);
                const uint32_t lo1 = *reinterpret_cast<uint32_t*>(&lp1);
                const int tr = grow & 127;
                char* hb = smem_raw + ((it < 4) ? T_AHI : T_BHI) + tr * 80 + seg * 8;
                char* lb = smem_raw + ((it < 4) ? T_ALO : T_BLO) + tr * 80 + seg * 8;
                *(uint2*)hb = make_uint2(hi0, hi1);
                *(uint2*)lb = make_uint2(lo0, lo1);
            }
        }
        __syncthreads();

        #pragma unroll
        for (int s = 0; s < 32; s += 16) {
            const int c0 = (s + qd) * 2;
            const int c1 = (s + qd + 8) * 2;
            uint32_t a[4][4], bh[4][2], bl[4][2];

            #pragma unroll
            for (int nt = 0; nt < 4; nt++) {
                const int ro = (wn + nt * 8 + g) * 80;
                bh[nt][0] = *(const uint32_t*)(smem_raw + T_BHI + ro + c0);
                bh[nt][1] = *(const uint32_t*)(smem_raw + T_BHI + ro + c1);
                bl[nt][0] = *(const uint32_t*)(smem_raw + T_BLO + ro + c0);
                bl[nt][1] = *(const uint32_t*)(smem_raw + T_BLO + ro + c1);
            }
            #pragma unroll
            for (int mt = 0; mt < 4; mt++) {
                const int r0 = (wm + mt * 16 + g) * 80;
                const int r1 = r0 + 8 * 80;
                a[mt][0] = *(const uint32_t*)(smem_raw + T_AHI + r0 + c0);
                a[mt][1] = *(const uint32_t*)(smem_raw + T_AHI + r1 + c0);
                a[mt][2] = *(const uint32_t*)(smem_raw + T_AHI + r0 + c1);
                a[mt][3] = *(const uint32_t*)(smem_raw + T_AHI + r1 + c1);
            }
            #pragma unroll
            for (int mt = 0; mt < 4; mt++)
                #pragma unroll
                for (int nt = 0; nt < 4; nt++)
                    mma_bf16(acc[mt][nt], a[mt], bh[nt]);   // Ahi*Bhi
            #pragma unroll
            for (int mt = 0; mt < 4; mt++)
                #pragma unroll
                for (int nt = 0; nt < 4; nt++)
                    mma_bf16(acc[mt][nt], a[mt], bl[nt]);   // Ahi*Blo
            #pragma unroll
            for (int mt = 0; mt < 4; mt++) {
                const int r0 = (wm + mt * 16 + g) * 80;
                const int r1 = r0 + 8 * 80;
                a[mt][0] = *(const uint32_t*)(smem_raw + T_ALO + r0 + c0);
                a[mt][1] = *(const uint32_t*)(smem_raw + T_ALO + r1 + c0);
                a[mt][2] = *(const uint32_t*)(smem_raw + T_ALO + r0 + c1);
                a[mt][3] = *(const uint32_t*)(smem_raw + T_ALO + r1 + c1);
            }
            #pragma unroll
            for (int mt = 0; mt < 4; mt++)
                #pragma unroll
                for (int nt = 0; nt < 4; nt++)
                    mma_bf16(acc[mt][nt], a[mt], bh[nt]);   // Alo*Bhi
        }
    }

    #pragma unroll
    for (int mt = 0; mt < 4; mt++) {
        #pragma unroll
        for (int hrow = 0; hrow < 2; hrow++) {
            const int row = rowBase + wm + mt * 16 + g + hrow * 8;
            bool zero = false;
            if (lengths) zero = ((row & 2047) >= lengths[row >> 11]);
            #pragma unroll
            for (int nt = 0; nt < 4; nt++) {
                const int col = colBase + wn + nt * 8 + qd;
                float v0 = acc[mt][nt][hrow * 2 + 0];
                float v1 = acc[mt][nt][hrow * 2 + 1];
                if (bias) { v0 += bias[col]; v1 += bias[col + 1]; }
                if (res) {
                    const float2 rr = *(const float2*)(res + (size_t)row * Cld + colOff + col);
                    v0 += rr.x; v1 += rr.y;
                }
                if (zero) { v0 = 0.0f; v1 = 0.0f; }
                *(float2*)(C + (size_t)row * Cld + colOff + col) = make_float2(v0, v1);
            }
        }
    }
}

// ---------------------------------------------------------------------------
// Flash attention (fp32, proven core). 1 thread = 1 query row.
// ---------------------------------------------------------------------------
__global__ __launch_bounds__(128)
void attn_kernel(const float* __restrict__ Q, int qStr,
                 const float* __restrict__ KV, int kvStr, int kOff, int vOff,
                 const int* __restrict__ lengths,
                 float* __restrict__ O, int kv_len)
{
    const int b = blockIdx.z;
    const int h = blockIdx.y;
    const int qrow = b * CN + blockIdx.x * 128 + threadIdx.x;

    float q[64];
    {
        const float4* qp = (const float4*)(Q + (size_t)qrow * qStr + h * CDH);
        #pragma unroll
        for (int d4 = 0; d4 < 16; d4++) {
            float4 t4 = qp[d4];
            q[4*d4+0] = t4.x * 0.125f; q[4*d4+1] = t4.y * 0.125f;
            q[4*d4+2] = t4.z * 0.125f; q[4*d4+3] = t4.w * 0.125f;
        }
    }

    float m = -1e30f, l = 0.0f;
    float acc[64];
    #pragma unroll
    for (int d = 0; d < 64; d++) acc[d] = 0.0f;

    const int valid = lengths ? lengths[b] : kv_len;
    const size_t kvBase = (size_t)b * kv_len;

    __shared__ float Ks[64][64];
    __shared__ float Vs[64][64];

    for (int t0 = 0; t0 < valid; t0 += 64) {
        const int tcount = min(64, valid - t0);
        for (int i = threadIdx.x; i < 64 * 16; i += 128) {
            const int r  = i >> 4;
            const int c4 = i & 15;
            const size_t base = (kvBase + t0 + r) * kvStr + h * CDH + c4 * 4;
            ((float4*)Ks[r])[c4] = *(const float4*)(KV + base + kOff);
            ((float4*)Vs[r])[c4] = *(const float4*)(KV + base + vOff);
        }
        __syncthreads();

        for (int j = 0; j < tcount; j++) {
            const float4* kr = (const float4*)Ks[j];
            float s = 0.0f;
            #pragma unroll
            for (int d4 = 0; d4 < 16; d4++) {
                float4 kk = kr[d4];
                s += q[4*d4+0]*kk.x + q[4*d4+1]*kk.y + q[4*d4+2]*kk.z + q[4*d4+3]*kk.w;
            }
            if (s > m) {
                const float c = __expf(m - s);
                l *= c;
                #pragma unroll
                for (int d = 0; d < 64; d++) acc[d] *= c;
                m = s;
            }
            const float pr = __expf(s - m);
            l += pr;
            const float4* vr = (const float4*)Vs[j];
            #pragma unroll
            for (int d4 = 0; d4 < 16; d4++) {
                float4 vv = vr[d4];
                acc[4*d4+0] += pr * vv.x; acc[4*d4+1] += pr * vv.y;
                acc[4*d4+2] += pr * vv.z; acc[4*d4+3] += pr * vv.w;
            }
        }
        __syncthreads();
    }

    const float inv = 1.0f / l;
    float4* op = (float4*)(O + (size_t)qrow * CINNER + h * CDH);
    #pragma unroll
    for (int d4 = 0; d4 < 16; d4++) {
        float4 o;
        o.x = acc[4*d4+0] * inv; o.y = acc[4*d4+1] * inv;
        o.z = acc[4*d4+2] * inv; o.w = acc[4*d4+3] * inv;
        op[d4] = o;
    }
}

// ---------------------------------------------------------------------------
// GEGLU (fp32, proven)
// ---------------------------------------------------------------------------
__global__ __launch_bounds__(256)
void geglu_kernel(const float* __restrict__ p, float* __restrict__ out)
{
    const size_t i = (size_t)blockIdx.x * 256 + threadIdx.x;
    const size_t row = i >> 11;
    const size_t col = i & 2047;
    const float a = p[row * 4096 + col];
    const float gt = p[row * 4096 + 2048 + col];
    const float gelu = 0.5f * gt * (1.0f + erff(gt * 0.70710678118654752f));
    out[i] = a * gelu;
}

// ---------------------------------------------------------------------------
// Launch
// ---------------------------------------------------------------------------
extern "C" void kernel_launch(void* const* d_in, const int* in_sizes, int n_in,
                              void* d_out, int out_size)
{
    (void)in_sizes; (void)n_in; (void)out_size;
    const float* x      = (const float*)d_in[0];
    const float* ctx    = (const float*)d_in[1];
    const int*   len    = (const int*)  d_in[2];
    const float* wq1    = (const float*)d_in[3];
    const float* wk1    = (const float*)d_in[4];
    const float* wv1    = (const float*)d_in[5];
    const float* wo1    = (const float*)d_in[6];
    const float* bo1    = (const float*)d_in[7];
    const float* wq2    = (const float*)d_in[8];
    const float* wk2    = (const float*)d_in[9];
    const float* wv2    = (const float*)d_in[10];
    const float* wo2    = (const float*)d_in[11];
    const float* bo2    = (const float*)d_in[12];
    const float* wff_in = (const float*)d_in[13];
    const float* bff_in = (const float*)d_in[14];
    const float* wff_out= (const float*)d_in[15];
    const float* bff_out= (const float*)d_in[16];
    const float* g1     = (const float*)d_in[17];
    const float* b1     = (const float*)d_in[18];
    const float* g2     = (const float*)d_in[19];
    const float* b2     = (const float*)d_in[20];
    const float* g3     = (const float*)d_in[21];
    const float* b3     = (const float*)d_in[22];
    float* out = (float*)d_out;

    cudaFuncSetAttribute(gemm_mma32, cudaFuncAttributeMaxDynamicSharedMemorySize, GSMEMT);

    float *h, *att, *gg, *qkv, *q2, *ckv, *x1, *x2, *p;
    float *wq1t, *wk1t, *wv1t, *wq2t, *wk2t, *wv2t, *wfit;
    cudaGetSymbolAddress((void**)&h,   g_h);
    cudaGetSymbolAddress((void**)&att, g_att);
    cudaGetSymbolAddress((void**)&gg,  g_gg);
    cudaGetSymbolAddress((void**)&qkv, g_qkv);
    cudaGetSymbolAddress((void**)&q2,  g_q2);
    cudaGetSymbolAddress((void**)&ckv, g_ckv);
    cudaGetSymbolAddress((void**)&x1,  g_x1);
    cudaGetSymbolAddress((void**)&x2,  g_x2);
    cudaGetSymbolAddress((void**)&p,   g_p);
    cudaGetSymbolAddress((void**)&wq1t, g_wq1t);
    cudaGetSymbolAddress((void**)&wk1t, g_wk1t);
    cudaGetSymbolAddress((void**)&wv1t, g_wv1t);
    cudaGetSymbolAddress((void**)&wq2t, g_wq2t);
    cudaGetSymbolAddress((void**)&wk2t, g_wk2t);
    cudaGetSymbolAddress((void**)&wv2t, g_wv2t);
    cudaGetSymbolAddress((void**)&wfit, g_wfit);

    const dim3 tb(32, 8);
    // ---- weight prep: transpose MMA weights (rowOff-free, validated) ----
    transp32<<<dim3(16, 16), tb>>>(wq1, 512, 512, wq1t);
    transp32<<<dim3(16, 16), tb>>>(wk1, 512, 512, wk1t);
    transp32<<<dim3(16, 16), tb>>>(wv1, 512, 512, wv1t);
    transp32<<<dim3(16, 16), tb>>>(wq2, 512, 512, wq2t);
    transp32<<<dim3(16, 24), tb>>>(wk2, 768, 512, wk2t);
    transp32<<<dim3(16, 24), tb>>>(wv2, 768, 512, wv2t);
    transp32<<<dim3(128, 16), tb>>>(wff_in, 512, 4096, wfit);

    const dim3 mP(4, 128);    // MMA: Nc=512,  M=16384
    const dim3 mC(4, 16);     // MMA: Nc=512,  M=2048
    const dim3 mF(32, 128);   // MMA: Nc=4096, M=16384 (validated shape)
    const dim3 gP(8, 256);    // gemm32: Nc=512, M=16384

    // ---- Phase 1: self-attention ----
    ln_kernel<<<CBN, 128>>>(x, g1, b1, h);
    gemm_mma32<<<mP, 256, GSMEMT>>>(h, wq1t, nullptr, nullptr, qkv, CBN, 512, 512, 1536, 0,    nullptr);
    gemm_mma32<<<mP, 256, GSMEMT>>>(h, wk1t, nullptr, nullptr, qkv, CBN, 512, 512, 1536, 512,  nullptr);
    gemm_mma32<<<mP, 256, GSMEMT>>>(h, wv1t, nullptr, nullptr, qkv, CBN, 512, 512, 1536, 1024, nullptr);
    attn_kernel<<<dim3(CN/128, CH, CB), 128>>>(qkv, 1536, qkv, 1536, 512, 1024,
        len, att, CN);
    gemm32<<<gP, 256>>>(att, wo1, bo1, x, x1, CBN, 512, 512, 512, 0, nullptr);

    // ---- Phase 2: cross-attention ----
    ln_kernel<<<CBN, 128>>>(x1, g2, b2, h);
    gemm_mma32<<<mP, 256, GSMEMT>>>(h, wq2t, nullptr, nullptr, q2, CBN, 512, 512, 512, 0, nullptr);
    gemm_mma32<<<mC, 256, GSMEMT>>>(ctx, wk2t, nullptr, nullptr, ckv, CBS, 512, 768, 1024, 0,   nullptr);
    gemm_mma32<<<mC, 256, GSMEMT>>>(ctx, wv2t, nullptr, nullptr, ckv, CBS, 512, 768, 1024, 512, nullptr);
    attn_kernel<<<dim3(CN/128, CH, CB), 128>>>(q2, 512, ckv, 1024, 0, 512,
        nullptr, att, CS);
    gemm32<<<gP, 256>>>(att, wo2, bo2, x1, x2, CBN, 512, 512, 512, 0, nullptr);

    // ---- Phase 3: GEGLU feed-forward ----
    ln_kernel<<<CBN, 128>>>(x2, g3, b3, h);
    gemm_mma32<<<mF, 256, GSMEMT>>>(h, wfit, bff_in, nullptr, p, CBN, 4096, 512, 4096, 0, nullptr);
    geglu_kernel<<<((size_t)CBN * CFF) / 256, 256>>>(p, gg);
    gemm32<<<gP, 256>>>(gg, wff_out, bff_out, x2, out, CBN, 512, 2048, 512, 0, len);
}

// round 10
// speedup vs baseline: 1.4740x; 1.0631x over previous
#include <cuda.h>
#include <cuda_runtime.h>
#include <cuda_bf16.h>
#include <math.h>
#include <stdint.h>

// ---------------------------------------------------------------------------
// Problem constants
// ---------------------------------------------------------------------------
#define CB   8
#define CN   2048
#define CD_  512
#define CS   256
#define CCD  768
#define CH   8
#define CDH  64
#define CINNER 512
#define CFF  2048
#define CBN  (CB*CN)    // 16384
#define CBS  (CB*CS)    // 2048

typedef unsigned long long u64;

// ---------------------------------------------------------------------------
// PTX helpers — family-safe only (all compile-proven on this toolchain)
// ---------------------------------------------------------------------------
__device__ __forceinline__ void cpa16(uint32_t dst, const void* src) {
    asm volatile("cp.async.ca.shared.global [%0], [%1], 16;" :: "r"(dst), "l"(src));
}
#define CP_COMMIT() asm volatile("cp.async.commit_group;" ::: "memory")
#define CP_WAIT(n)  asm volatile("cp.async.wait_group %0;" :: "n"(n) : "memory")

__device__ __forceinline__ uint32_t smem_u32(const void* p) {
    uint32_t a;
    asm("{ .reg .u64 t; cvta.to.shared.u64 t, %1; cvt.u32.u64 %0, t; }"
        : "=r"(a) : "l"(p));
    return a;
}

__device__ __forceinline__ void mma_bf16(float* c, const uint32_t* a, const uint32_t* b) {
    asm volatile("mma.sync.aligned.m16n8k16.row.col.f32.bf16.bf16.f32 "
                 "{%0,%1,%2,%3}, {%4,%5,%6,%7}, {%8,%9}, {%0,%1,%2,%3};"
                 : "+f"(c[0]), "+f"(c[1]), "+f"(c[2]), "+f"(c[3])
                 : "r"(a[0]), "r"(a[1]), "r"(a[2]), "r"(a[3]), "r"(b[0]), "r"(b[1]));
}

// packed fp32x2 math (compile-proven in Round-3 binary)
__device__ __forceinline__ u64 fma2(u64 a, u64 b, u64 c) {
    u64 d; asm("fma.rn.f32x2 %0,%1,%2,%3;" : "=l"(d) : "l"(a), "l"(b), "l"(c)); return d;
}
__device__ __forceinline__ u64 mul2(u64 a, u64 b) {
    u64 d; asm("mul.rn.f32x2 %0,%1,%2;" : "=l"(d) : "l"(a), "l"(b)); return d;
}
__device__ __forceinline__ u64 add2(u64 a, u64 b) {
    u64 d; asm("add.rn.f32x2 %0,%1,%2;" : "=l"(d) : "l"(a), "l"(b)); return d;
}
__device__ __forceinline__ u64 pack2(float lo, float hi) {
    u64 r; asm("mov.b64 %0,{%1,%2};" : "=l"(r) : "f"(lo), "f"(hi)); return r;
}
__device__ __forceinline__ void unpack2(u64 v, float& lo, float& hi) {
    asm("mov.b64 {%0,%1},%2;" : "=f"(lo), "=f"(hi) : "l"(v));
}

// ---------------------------------------------------------------------------
// Scratch (static device globals)
// ---------------------------------------------------------------------------
__device__ float g_h  [(size_t)CBN * CD_];
__device__ float g_att[(size_t)CBN * CINNER];
__device__ float g_gg [(size_t)CBN * CFF];
__device__ float g_qkv[(size_t)CBN * 1536];   // interleaved [row][q|k|v]
__device__ float g_q2 [(size_t)CBN * 512];
__device__ float g_ckv[(size_t)CBS * 1024];   // interleaved [row][k|v]
__device__ float g_x1 [(size_t)CBN * 512];
__device__ float g_x2 [(size_t)CBN * 512];
__device__ float g_p  [(size_t)CBN * 4096];
// transposed weights [N,K] fp32 (for MMA GEMMs only); others stay [K,N]
__device__ float g_wq1t[512 * 512];
__device__ float g_wk1t[512 * 512];
__device__ float g_wv1t[512 * 512];
__device__ float g_wq2t[512 * 512];
__device__ float g_wk2t[512 * 768];
__device__ float g_wv2t[512 * 768];
__device__ float g_wfit[4096 * 512];

// ---------------------------------------------------------------------------
// Weight transpose (fp32): W[K,N] -> out[N,K].  block (32,8), grid (N/32,K/32)
// ---------------------------------------------------------------------------
__global__ __launch_bounds__(256)
void transp32(const float* __restrict__ W, int K, int N, float* __restrict__ o)
{
    __shared__ float t[32][33];
    const int k0 = blockIdx.y * 32, n0 = blockIdx.x * 32;
    const int tx = threadIdx.x, ty = threadIdx.y;
    #pragma unroll
    for (int i = 0; i < 4; i++)
        t[ty + i * 8][tx] = W[(size_t)(k0 + ty + i * 8) * N + n0 + tx];
    __syncthreads();
    #pragma unroll
    for (int i = 0; i < 4; i++) {
        const int n = n0 + ty + i * 8, k = k0 + tx;
        o[(size_t)n * K + k] = t[tx][ty + i * 8];
    }
}

// ---------------------------------------------------------------------------
// LayerNorm (fp32). [proven]
// ---------------------------------------------------------------------------
__global__ __launch_bounds__(128)
void ln_kernel(const float* __restrict__ in, const float* __restrict__ gamma,
               const float* __restrict__ beta, float* __restrict__ out)
{
    const int row = blockIdx.x;
    const int t   = threadIdx.x;
    const float4 v = ((const float4*)(in + (size_t)row * CD_))[t];

    float s  = v.x + v.y + v.z + v.w;
    float ss = v.x*v.x + v.y*v.y + v.z*v.z + v.w*v.w;
    #pragma unroll
    for (int o = 16; o > 0; o >>= 1) {
        s  += __shfl_xor_sync(0xFFFFFFFFu, s,  o);
        ss += __shfl_xor_sync(0xFFFFFFFFu, ss, o);
    }
    __shared__ float sh[8];
    if ((t & 31) == 0) { sh[t >> 5] = s; sh[4 + (t >> 5)] = ss; }
    __syncthreads();
    s  = sh[0] + sh[1] + sh[2] + sh[3];
    ss = sh[4] + sh[5] + sh[6] + sh[7];

    const float mean = s * (1.0f / CD_);
    const float rstd = rsqrtf(ss * (1.0f / CD_) - mean * mean + 1e-5f);

    const float4 gv = ((const float4*)gamma)[t];
    const float4 bv = ((const float4*)beta)[t];
    float4 o;
    o.x = (v.x - mean) * rstd * gv.x + bv.x;
    o.y = (v.y - mean) * rstd * gv.y + bv.y;
    o.z = (v.z - mean) * rstd * gv.z + bv.z;
    o.w = (v.w - mean) * rstd * gv.w + bv.w;
    ((float4*)(out + (size_t)row * CD_))[t] = o;
}

// ---------------------------------------------------------------------------
// R1-proven fp32 SGEMM + Cld/colOff (R6/R8-validated structure). Inner loop
// upgraded to fma.rn.f32x2 — same operands, same order, lane-wise IEEE fma
// => bit-identical results to the FFMA version.
// ---------------------------------------------------------------------------
__global__ __launch_bounds__(256)
void gemm32(const float* __restrict__ A, const float* __restrict__ W,
            const float* __restrict__ bias, const float* __restrict__ res,
            float* __restrict__ C, int M, int Nc, int K,
            int Cld, int colOff, const int* __restrict__ lengths)
{
    __shared__ __align__(16) float As[16][64];
    __shared__ __align__(16) float Bs[16][64];

    const int tid  = threadIdx.x;
    const int tx   = tid & 15;
    const int ty   = tid >> 4;
    const int aRow = tid >> 2;
    const int aC4  = tid & 3;
    const int bRow = tid >> 4;
    const int bC4  = tid & 15;

    const int rowBase = blockIdx.y * 64;
    const int colBase = blockIdx.x * 64;

    u64 acc2[4][2];
    #pragma unroll
    for (int i = 0; i < 4; i++) { acc2[i][0] = 0ull; acc2[i][1] = 0ull; }

    for (int k0 = 0; k0 < K; k0 += 16) {
        float4 a = *(const float4*)(A + (size_t)(rowBase + aRow) * K + k0 + aC4 * 4);
        As[aC4 * 4 + 0][aRow] = a.x;
        As[aC4 * 4 + 1][aRow] = a.y;
        As[aC4 * 4 + 2][aRow] = a.z;
        As[aC4 * 4 + 3][aRow] = a.w;
        *(float4*)&Bs[bRow][bC4 * 4] =
            *(const float4*)(W + (size_t)(k0 + bRow) * Nc + colBase + bC4 * 4);
        __syncthreads();

        #pragma unroll
        for (int kk = 0; kk < 16; kk++) {
            const float4 av = *(const float4*)&As[kk][ty * 4];
            const ulonglong2 bv = *(const ulonglong2*)&Bs[kk][tx * 4];
            float ar[4] = {av.x, av.y, av.z, av.w};
            #pragma unroll
            for (int i = 0; i < 4; i++) {
                const u64 aa = pack2(ar[i], ar[i]);
                acc2[i][0] = fma2(aa, bv.x, acc2[i][0]);
                acc2[i][1] = fma2(aa, bv.y, acc2[i][1]);
            }
        }
        __syncthreads();
    }

    #pragma unroll
    for (int i = 0; i < 4; i++) {
        const int row = rowBase + ty * 4 + i;
        bool zero = false;
        if (lengths) {
            const int b = row >> 11;
            const int n = row & 2047;
            zero = (n >= lengths[b]);
        }
        const int col = colBase + tx * 4;
        float vv[4];
        unpack2(acc2[i][0], vv[0], vv[1]);
        unpack2(acc2[i][1], vv[2], vv[3]);
        #pragma unroll
        for (int j = 0; j < 4; j++) {
            float val = vv[j];
            if (bias) val += bias[col + j];
            if (res)  val += res[(size_t)row * Cld + col + j];
            vv[j] = zero ? 0.0f : val;
        }
        float4 o;
        o.x = vv[0]; o.y = vv[1]; o.z = vv[2]; o.w = vv[3];
        *(float4*)(C + (size_t)row * Cld + colOff + col) = o;
    }
}

// ---------------------------------------------------------------------------
// HMMA bf16x3 GEMM, in-kernel truncation hi/lo split [R8-validated VERBATIM]
// ---------------------------------------------------------------------------
#define T_AHI 0
#define T_ALO 10240
#define T_BHI 20480
#define T_BLO 30720
#define STG_OFF 40960
#define STG_SZ  32768
#define GSMEMT (STG_OFF + 2 * STG_SZ)

__global__ __launch_bounds__(256, 2)
void gemm_mma32(const float* __restrict__ A, const float* __restrict__ B,
                const float* __restrict__ bias, const float* __restrict__ res,
                float* __restrict__ C, int M, int Nc, int K,
                int Cld, int colOff, const int* __restrict__ lengths)
{
    extern __shared__ __align__(1024) char smem_raw[];
    const uint32_t sb = smem_u32(smem_raw);
    const int tid = threadIdx.x;
    const int wid = tid >> 5, l = tid & 31;
    const int wm = (wid >> 2) * 64;
    const int wn = (wid & 3) * 32;
    const int g  = l >> 2;
    const int qd = (l & 3) * 2;

    const int rowBase = blockIdx.y * 128;
    const int colBase = blockIdx.x * 128;

    const int seg = tid & 7;
    const int rb  = tid >> 3;

    float acc[4][4][4];
    #pragma unroll
    for (int a = 0; a < 4; a++)
        #pragma unroll
        for (int b = 0; b < 4; b++)
            #pragma unroll
            for (int c = 0; c < 4; c++) acc[a][b][c] = 0.0f;

    const int nch = K >> 5;

    #pragma unroll
    for (int it = 0; it < 8; it++) {
        const int grow = rb + it * 32;
        const float* src = (it < 4) ? (A + (size_t)(rowBase + grow) * K)
                                    : (B + (size_t)(colBase + grow - 128) * K);
        cpa16(sb + STG_OFF + (uint32_t)(grow * 128 + seg * 16), src + seg * 4);
    }
    CP_COMMIT();

    for (int ck = 0; ck < nch; ck++) {
        if (ck + 1 < nch) {
            const int kb = (ck + 1) * 32;
            const uint32_t ds = sb + STG_OFF + (uint32_t)(((ck + 1) & 1) * STG_SZ);
            #pragma unroll
            for (int it = 0; it < 8; it++) {
                const int grow = rb + it * 32;
                const float* src = (it < 4) ? (A + (size_t)(rowBase + grow) * K)
                                            : (B + (size_t)(colBase + grow - 128) * K);
                cpa16(ds + (uint32_t)(grow * 128 + seg * 16), src + kb + seg * 4);
            }
            CP_COMMIT();
            CP_WAIT(1);
        } else {
            CP_WAIT(0);
        }
        __syncthreads();

        {
            const char* sp = smem_raw + STG_OFF + (size_t)(ck & 1) * STG_SZ;
            #pragma unroll
            for (int it = 0; it < 8; it++) {
                const int grow = rb + it * 32;
                const float4 v = *(const float4*)(sp + grow * 128 + seg * 16);
                const uint32_t u0 = __float_as_uint(v.x), u1 = __float_as_uint(v.y);
                const uint32_t u2 = __float_as_uint(v.z), u3 = __float_as_uint(v.w);
                const uint32_t hi0 = (u0 >> 16) | (u1 & 0xFFFF0000u);
                const uint32_t hi1 = (u2 >> 16) | (u3 & 0xFFFF0000u);
                const float l0 = v.x - __uint_as_float(u0 & 0xFFFF0000u);
                const float l1 = v.y - __uint_as_float(u1 & 0xFFFF0000u);
                const float l2 = v.z - __uint_as_float(u2 & 0xFFFF0000u);
                const float l3 = v.w - __uint_as_float(u3 & 0xFFFF0000u);
                __nv_bfloat162 lp0 = __floats2bfloat162_rn(l0, l1);
                __nv_bfloat162 lp1 = __floats2bfloat162_rn(l2, l3);
                const uint32_t lo0 = *reinterpret_cast<uint32_t*>(&lp0);
                const uint32_t lo1 = *reinterpret_cast<uint32_t*>(&lp1);
                const int tr = grow & 127;
                char* hb = smem_raw + ((it < 4) ? T_AHI : T_BHI) + tr * 80 + seg * 8;
                char* lb = smem_raw + ((it < 4) ? T_ALO : T_BLO) + tr * 80 + seg * 8;
                *(uint2*)hb = make_uint2(hi0, hi1);
                *(uint2*)lb = make_uint2(lo0, lo1);
            }
        }
        __syncthreads();

        #pragma unroll
        for (int s = 0; s < 32; s += 16) {
            const int c0 = (s + qd) * 2;
            const int c1 = (s + qd + 8) * 2;
            uint32_t a[4][4], bh[4][2], bl[4][2];

            #pragma unroll
            for (int nt = 0; nt < 4; nt++) {
                const int ro = (wn + nt * 8 + g) * 80;
                bh[nt][0] = *(const uint32_t*)(smem_raw + T_BHI + ro + c0);
                bh[nt][1] = *(const uint32_t*)(smem_raw + T_BHI + ro + c1);
                bl[nt][0] = *(const uint32_t*)(smem_raw + T_BLO + ro + c0);
                bl[nt][1] = *(const uint32_t*)(smem_raw + T_BLO + ro + c1);
            }
            #pragma unroll
            for (int mt = 0; mt < 4; mt++) {
                const int r0 = (wm + mt * 16 + g) * 80;
                const int r1 = r0 + 8 * 80;
                a[mt][0] = *(const uint32_t*)(smem_raw + T_AHI + r0 + c0);
                a[mt][1] = *(const uint32_t*)(smem_raw + T_AHI + r1 + c0);
                a[mt][2] = *(const uint32_t*)(smem_raw + T_AHI + r0 + c1);
                a[mt][3] = *(const uint32_t*)(smem_raw + T_AHI + r1 + c1);
            }
            #pragma unroll
            for (int mt = 0; mt < 4; mt++)
                #pragma unroll
                for (int nt = 0; nt < 4; nt++)
                    mma_bf16(acc[mt][nt], a[mt], bh[nt]);   // Ahi*Bhi
            #pragma unroll
            for (int mt = 0; mt < 4; mt++)
                #pragma unroll
                for (int nt = 0; nt < 4; nt++)
                    mma_bf16(acc[mt][nt], a[mt], bl[nt]);   // Ahi*Blo
            #pragma unroll
            for (int mt = 0; mt < 4; mt++) {
                const int r0 = (wm + mt * 16 + g) * 80;
                const int r1 = r0 + 8 * 80;
                a[mt][0] = *(const uint32_t*)(smem_raw + T_ALO + r0 + c0);
                a[mt][1] = *(const uint32_t*)(smem_raw + T_ALO + r1 + c0);
                a[mt][2] = *(const uint32_t*)(smem_raw + T_ALO + r0 + c1);
                a[mt][3] = *(const uint32_t*)(smem_raw + T_ALO + r1 + c1);
            }
            #pragma unroll
            for (int mt = 0; mt < 4; mt++)
                #pragma unroll
                for (int nt = 0; nt < 4; nt++)
                    mma_bf16(acc[mt][nt], a[mt], bh[nt]);   // Alo*Bhi
        }
    }

    #pragma unroll
    for (int mt = 0; mt < 4; mt++) {
        #pragma unroll
        for (int hrow = 0; hrow < 2; hrow++) {
            const int row = rowBase + wm + mt * 16 + g + hrow * 8;
            bool zero = false;
            if (lengths) zero = ((row & 2047) >= lengths[row >> 11]);
            #pragma unroll
            for (int nt = 0; nt < 4; nt++) {
                const int col = colBase + wn + nt * 8 + qd;
                float v0 = acc[mt][nt][hrow * 2 + 0];
                float v1 = acc[mt][nt][hrow * 2 + 1];
                if (bias) { v0 += bias[col]; v1 += bias[col + 1]; }
                if (res) {
                    const float2 rr = *(const float2*)(res + (size_t)row * Cld + colOff + col);
                    v0 += rr.x; v1 += rr.y;
                }
                if (zero) { v0 = 0.0f; v1 = 0.0f; }
                *(float2*)(C + (size_t)row * Cld + colOff + col) = make_float2(v0, v1);
            }
        }
    }
}

// ---------------------------------------------------------------------------
// Flash attention — proven control flow, arithmetic upgraded to f32x2.
// 1 thread = 1 query row.
// ---------------------------------------------------------------------------
__global__ __launch_bounds__(128)
void attn_kernel(const float* __restrict__ Q, int qStr,
                 const float* __restrict__ KV, int kvStr, int kOff, int vOff,
                 const int* __restrict__ lengths,
                 float* __restrict__ O, int kv_len)
{
    const int b = blockIdx.z;
    const int h = blockIdx.y;
    const int qrow = b * CN + blockIdx.x * 128 + threadIdx.x;

    u64 q2r[32];
    {
        const float4* qp = (const float4*)(Q + (size_t)qrow * qStr + h * CDH);
        #pragma unroll
        for (int d4 = 0; d4 < 16; d4++) {
            float4 t4 = qp[d4];
            q2r[2*d4]   = pack2(t4.x * 0.125f, t4.y * 0.125f);
            q2r[2*d4+1] = pack2(t4.z * 0.125f, t4.w * 0.125f);
        }
    }

    float m = -1e30f, l = 0.0f;
    u64 acc2[32];
    #pragma unroll
    for (int d = 0; d < 32; d++) acc2[d] = 0ull;

    const int valid = lengths ? lengths[b] : kv_len;
    const size_t kvBase = (size_t)b * kv_len;

    __shared__ __align__(16) float Ks[64][64];
    __shared__ __align__(16) float Vs[64][64];

    for (int t0 = 0; t0 < valid; t0 += 64) {
        const int tcount = min(64, valid - t0);
        for (int i = threadIdx.x; i < 64 * 16; i += 128) {
            const int r  = i >> 4;
            const int c4 = i & 15;
            const size_t base = (kvBase + t0 + r) * kvStr + h * CDH + c4 * 4;
            ((float4*)Ks[r])[c4] = *(const float4*)(KV + base + kOff);
            ((float4*)Vs[r])[c4] = *(const float4*)(KV + base + vOff);
        }
        __syncthreads();

        for (int j = 0; j < tcount; j++) {
            const ulonglong2* kr = (const ulonglong2*)Ks[j];
            u64 p0 = 0ull, p1 = 0ull, p2 = 0ull, p3 = 0ull;
            #pragma unroll
            for (int i = 0; i < 16; i += 2) {
                const ulonglong2 k0 = kr[i], k1 = kr[i + 1];
                p0 = fma2(q2r[2*i],   k0.x, p0);
                p1 = fma2(q2r[2*i+1], k0.y, p1);
                p2 = fma2(q2r[2*i+2], k1.x, p2);
                p3 = fma2(q2r[2*i+3], k1.y, p3);
            }
            float sa, sb2;
            unpack2(add2(add2(p0, p1), add2(p2, p3)), sa, sb2);
            const float s = sa + sb2;

            if (s > m) {
                const float c = __expf(m - s);
                const u64 c2 = pack2(c, c);
                l *= c;
                #pragma unroll
                for (int d = 0; d < 32; d++) acc2[d] = mul2(acc2[d], c2);
                m = s;
            }
            const float pr = __expf(s - m);
            l += pr;
            const u64 pr2 = pack2(pr, pr);
            const ulonglong2* vr = (const ulonglong2*)Vs[j];
            #pragma unroll
            for (int i = 0; i < 16; i++) {
                const ulonglong2 v = vr[i];
                acc2[2*i]   = fma2(pr2, v.x, acc2[2*i]);
                acc2[2*i+1] = fma2(pr2, v.y, acc2[2*i+1]);
            }
        }
        __syncthreads();
    }

    const float inv = 1.0f / l;
    float4* op = (float4*)(O + (size_t)qrow * CINNER + h * CDH);
    #pragma unroll
    for (int d4 = 0; d4 < 16; d4++) {
        float o0, o1, o2, o3;
        unpack2(acc2[2*d4],   o0, o1);
        unpack2(acc2[2*d4+1], o2, o3);
        float4 o;
        o.x = o0 * inv; o.y = o1 * inv; o.z = o2 * inv; o.w = o3 * inv;
        op[d4] = o;
    }
}

// ---------------------------------------------------------------------------
// GEGLU (fp32, proven)
// ---------------------------------------------------------------------------
__global__ __launch_bounds__(256)
void geglu_kernel(const float* __restrict__ p, float* __restrict__ out)
{
    const size_t i = (size_t)blockIdx.x * 256 + threadIdx.x;
    const size_t row = i >> 11;
    const size_t col = i & 2047;
    const float a = p[row * 4096 + col];
    const float gt = p[row * 4096 + 2048 + col];
    const float gelu = 0.5f * gt * (1.0f + erff(gt * 0.70710678118654752f));
    out[i] = a * gelu;
}

// ---------------------------------------------------------------------------
// Launch (R8-passing structure, verbatim)
// ---------------------------------------------------------------------------
extern "C" void kernel_launch(void* const* d_in, const int* in_sizes, int n_in,
                              void* d_out, int out_size)
{
    (void)in_sizes; (void)n_in; (void)out_size;
    const float* x      = (const float*)d_in[0];
    const float* ctx    = (const float*)d_in[1];
    const int*   len    = (const int*)  d_in[2];
    const float* wq1    = (const float*)d_in[3];
    const float* wk1    = (const float*)d_in[4];
    const float* wv1    = (const float*)d_in[5];
    const float* wo1    = (const float*)d_in[6];
    const float* bo1    = (const float*)d_in[7];
    const float* wq2    = (const float*)d_in[8];
    const float* wk2    = (const float*)d_in[9];
    const float* wv2    = (const float*)d_in[10];
    const float* wo2    = (const float*)d_in[11];
    const float* bo2    = (const float*)d_in[12];
    const float* wff_in = (const float*)d_in[13];
    const float* bff_in = (const float*)d_in[14];
    const float* wff_out= (const float*)d_in[15];
    const float* bff_out= (const float*)d_in[16];
    const float* g1     = (const float*)d_in[17];
    const float* b1     = (const float*)d_in[18];
    const float* g2     = (const float*)d_in[19];
    const float* b2     = (const float*)d_in[20];
    const float* g3     = (const float*)d_in[21];
    const float* b3     = (const float*)d_in[22];
    float* out = (float*)d_out;

    cudaFuncSetAttribute(gemm_mma32, cudaFuncAttributeMaxDynamicSharedMemorySize, GSMEMT);

    float *h, *att, *gg, *qkv, *q2, *ckv, *x1, *x2, *p;
    float *wq1t, *wk1t, *wv1t, *wq2t, *wk2t, *wv2t, *wfit;
    cudaGetSymbolAddress((void**)&h,   g_h);
    cudaGetSymbolAddress((void**)&att, g_att);
    cudaGetSymbolAddress((void**)&gg,  g_gg);
    cudaGetSymbolAddress((void**)&qkv, g_qkv);
    cudaGetSymbolAddress((void**)&q2,  g_q2);
    cudaGetSymbolAddress((void**)&ckv, g_ckv);
    cudaGetSymbolAddress((void**)&x1,  g_x1);
    cudaGetSymbolAddress((void**)&x2,  g_x2);
    cudaGetSymbolAddress((void**)&p,   g_p);
    cudaGetSymbolAddress((void**)&wq1t, g_wq1t);
    cudaGetSymbolAddress((void**)&wk1t, g_wk1t);
    cudaGetSymbolAddress((void**)&wv1t, g_wv1t);
    cudaGetSymbolAddress((void**)&wq2t, g_wq2t);
    cudaGetSymbolAddress((void**)&wk2t, g_wk2t);
    cudaGetSymbolAddress((void**)&wv2t, g_wv2t);
    cudaGetSymbolAddress((void**)&wfit, g_wfit);

    const dim3 tb(32, 8);
    transp32<<<dim3(16, 16), tb>>>(wq1, 512, 512, wq1t);
    transp32<<<dim3(16, 16), tb>>>(wk1, 512, 512, wk1t);
    transp32<<<dim3(16, 16), tb>>>(wv1, 512, 512, wv1t);
    transp32<<<dim3(16, 16), tb>>>(wq2, 512, 512, wq2t);
    transp32<<<dim3(16, 24), tb>>>(wk2, 768, 512, wk2t);
    transp32<<<dim3(16, 24), tb>>>(wv2, 768, 512, wv2t);
    transp32<<<dim3(128, 16), tb>>>(wff_in, 512, 4096, wfit);

    const dim3 mP(4, 128);    // MMA: Nc=512,  M=16384
    const dim3 mC(4, 16);     // MMA: Nc=512,  M=2048
    const dim3 mF(32, 128);   // MMA: Nc=4096, M=16384
    const dim3 gP(8, 256);    // gemm32: Nc=512, M=16384

    // ---- Phase 1: self-attention ----
    ln_kernel<<<CBN, 128>>>(x, g1, b1, h);
    gemm_mma32<<<mP, 256, GSMEMT>>>(h, wq1t, nullptr, nullptr, qkv, CBN, 512, 512, 1536, 0,    nullptr);
    gemm_mma32<<<mP, 256, GSMEMT>>>(h, wk1t, nullptr, nullptr, qkv, CBN, 512, 512, 1536, 512,  nullptr);
    gemm_mma32<<<mP, 256, GSMEMT>>>(h, wv1t, nullptr, nullptr, qkv, CBN, 512, 512, 1536, 1024, nullptr);
    attn_kernel<<<dim3(CN/128, CH, CB), 128>>>(qkv, 1536, qkv, 1536, 512, 1024,
        len, att, CN);
    gemm32<<<gP, 256>>>(att, wo1, bo1, x, x1, CBN, 512, 512, 512, 0, nullptr);

    // ---- Phase 2: cross-attention ----
    ln_kernel<<<CBN, 128>>>(x1, g2, b2, h);
    gemm_mma32<<<mP, 256, GSMEMT>>>(h, wq2t, nullptr, nullptr, q2, CBN, 512, 512, 512, 0, nullptr);
    gemm_mma32<<<mC, 256, GSMEMT>>>(ctx, wk2t, nullptr, nullptr, ckv, CBS, 512, 768, 1024, 0,   nullptr);
    gemm_mma32<<<mC, 256, GSMEMT>>>(ctx, wv2t, nullptr, nullptr, ckv, CBS, 512, 768, 1024, 512, nullptr);
    attn_kernel<<<dim3(CN/128, CH, CB), 128>>>(q2, 512, ckv, 1024, 0, 512,
        nullptr, att, CS);
    gemm32<<<gP, 256>>>(att, wo2, bo2, x1, x2, CBN, 512, 512, 512, 0, nullptr);

    // ---- Phase 3: GEGLU feed-forward ----
    ln_kernel<<<CBN, 128>>>(x2, g3, b3, h);
    gemm_mma32<<<mF, 256, GSMEMT>>>(h, wfit, bff_in, nullptr, p, CBN, 4096, 512, 4096, 0, nullptr);
    geglu_kernel<<<((size_t)CBN * CFF) / 256, 256>>>(p, gg);
    gemm32<<<gP, 256>>>(gg, wff_out, bff_out, x2, out, CBN, 512, 2048, 512, 0, len);
}

// round 11
// speedup vs baseline: 1.4988x; 1.0168x over previous
#include <cuda.h>
#include <cuda_runtime.h>
#include <cuda_bf16.h>
#include <math.h>
#include <stdint.h>

// ---------------------------------------------------------------------------
// Problem constants
// ---------------------------------------------------------------------------
#define CB   8
#define CN   2048
#define CD_  512
#define CS   256
#define CCD  768
#define CH   8
#define CDH  64
#define CINNER 512
#define CFF  2048
#define CBN  (CB*CN)    // 16384
#define CBS  (CB*CS)    // 2048

typedef unsigned long long u64;

// ---------------------------------------------------------------------------
// PTX helpers — family-safe only
// ---------------------------------------------------------------------------
__device__ __forceinline__ void cpa16(uint32_t dst, const void* src) {
    asm volatile("cp.async.ca.shared.global [%0], [%1], 16;" :: "r"(dst), "l"(src));
}
#define CP_COMMIT() asm volatile("cp.async.commit_group;" ::: "memory")
#define CP_WAIT(n)  asm volatile("cp.async.wait_group %0;" :: "n"(n) : "memory")

__device__ __forceinline__ uint32_t smem_u32(const void* p) {
    uint32_t a;
    asm("{ .reg .u64 t; cvta.to.shared.u64 t, %1; cvt.u32.u64 %0, t; }"
        : "=r"(a) : "l"(p));
    return a;
}

__device__ __forceinline__ void mma_bf16(float* c, const uint32_t* a, const uint32_t* b) {
    asm volatile("mma.sync.aligned.m16n8k16.row.col.f32.bf16.bf16.f32 "
                 "{%0,%1,%2,%3}, {%4,%5,%6,%7}, {%8,%9}, {%0,%1,%2,%3};"
                 : "+f"(c[0]), "+f"(c[1]), "+f"(c[2]), "+f"(c[3])
                 : "r"(a[0]), "r"(a[1]), "r"(a[2]), "r"(a[3]), "r"(b[0]), "r"(b[1]));
}

__device__ __forceinline__ u64 fma2(u64 a, u64 b, u64 c) {
    u64 d; asm("fma.rn.f32x2 %0,%1,%2,%3;" : "=l"(d) : "l"(a), "l"(b), "l"(c)); return d;
}
__device__ __forceinline__ u64 mul2(u64 a, u64 b) {
    u64 d; asm("mul.rn.f32x2 %0,%1,%2;" : "=l"(d) : "l"(a), "l"(b)); return d;
}
__device__ __forceinline__ u64 add2(u64 a, u64 b) {
    u64 d; asm("add.rn.f32x2 %0,%1,%2;" : "=l"(d) : "l"(a), "l"(b)); return d;
}
__device__ __forceinline__ u64 pack2(float lo, float hi) {
    u64 r; asm("mov.b64 %0,{%1,%2};" : "=l"(r) : "f"(lo), "f"(hi)); return r;
}
__device__ __forceinline__ void unpack2(u64 v, float& lo, float& hi) {
    asm("mov.b64 {%0,%1},%2;" : "=f"(lo), "=f"(hi) : "l"(v));
}

// ---------------------------------------------------------------------------
// Scratch (static device globals)
// ---------------------------------------------------------------------------
__device__ float g_h  [(size_t)CBN * CD_];
__device__ float g_att[(size_t)CBN * CINNER];
__device__ float g_gg [(size_t)CBN * CFF];
__device__ float g_qkv[(size_t)CBN * 1536];   // interleaved [row][q|k|v]
__device__ float g_q2 [(size_t)CBN * 512];
__device__ float g_ckv[(size_t)CBS * 1024];   // interleaved [row][k|v]
__device__ float g_x1 [(size_t)CBN * 512];
__device__ float g_x2 [(size_t)CBN * 512];
__device__ float g_p  [(size_t)CBN * 4096];
__device__ float g_wq1t[512 * 512];
__device__ float g_wk1t[512 * 512];
__device__ float g_wv1t[512 * 512];
__device__ float g_wq2t[512 * 512];
__device__ float g_wk2t[512 * 768];
__device__ float g_wv2t[512 * 768];
__device__ float g_wfit[4096 * 512];

// ---------------------------------------------------------------------------
// Weight transpose (fp32): W[K,N] -> out[N,K]
// ---------------------------------------------------------------------------
__global__ __launch_bounds__(256)
void transp32(const float* __restrict__ W, int K, int N, float* __restrict__ o)
{
    __shared__ float t[32][33];
    const int k0 = blockIdx.y * 32, n0 = blockIdx.x * 32;
    const int tx = threadIdx.x, ty = threadIdx.y;
    #pragma unroll
    for (int i = 0; i < 4; i++)
        t[ty + i * 8][tx] = W[(size_t)(k0 + ty + i * 8) * N + n0 + tx];
    __syncthreads();
    #pragma unroll
    for (int i = 0; i < 4; i++) {
        const int n = n0 + ty + i * 8, k = k0 + tx;
        o[(size_t)n * K + k] = t[tx][ty + i * 8];
    }
}

// ---------------------------------------------------------------------------
// LayerNorm (fp32). [proven]
// ---------------------------------------------------------------------------
__global__ __launch_bounds__(128)
void ln_kernel(const float* __restrict__ in, const float* __restrict__ gamma,
               const float* __restrict__ beta, float* __restrict__ out)
{
    const int row = blockIdx.x;
    const int t   = threadIdx.x;
    const float4 v = ((const float4*)(in + (size_t)row * CD_))[t];

    float s  = v.x + v.y + v.z + v.w;
    float ss = v.x*v.x + v.y*v.y + v.z*v.z + v.w*v.w;
    #pragma unroll
    for (int o = 16; o > 0; o >>= 1) {
        s  += __shfl_xor_sync(0xFFFFFFFFu, s,  o);
        ss += __shfl_xor_sync(0xFFFFFFFFu, ss, o);
    }
    __shared__ float sh[8];
    if ((t & 31) == 0) { sh[t >> 5] = s; sh[4 + (t >> 5)] = ss; }
    __syncthreads();
    s  = sh[0] + sh[1] + sh[2] + sh[3];
    ss = sh[4] + sh[5] + sh[6] + sh[7];

    const float mean = s * (1.0f / CD_);
    const float rstd = rsqrtf(ss * (1.0f / CD_) - mean * mean + 1e-5f);

    const float4 gv = ((const float4*)gamma)[t];
    const float4 bv = ((const float4*)beta)[t];
    float4 o;
    o.x = (v.x - mean) * rstd * gv.x + bv.x;
    o.y = (v.y - mean) * rstd * gv.y + bv.y;
    o.z = (v.z - mean) * rstd * gv.z + bv.z;
    o.w = (v.w - mean) * rstd * gv.w + bv.w;
    ((float4*)(out + (size_t)row * CD_))[t] = o;
}

// ---------------------------------------------------------------------------
// fp32 SGEMM v2: BM=128, BN=64, BK=16, 256 threads, 8x4 micro-tile with
// row-paired u64 A operands (no A-side packs). Same epilogue semantics as the
// proven gemm32 (bias/res/mask, Cld/colOff addressing).
// ---------------------------------------------------------------------------
__global__ __launch_bounds__(256)
void gemm32(const float* __restrict__ A, const float* __restrict__ W,
            const float* __restrict__ bias, const float* __restrict__ res,
            float* __restrict__ C, int M, int Nc, int K,
            int Cld, int colOff, const int* __restrict__ lengths)
{
    __shared__ __align__(16) float As[16][128];
    __shared__ __align__(16) float Bs[16][64];

    const int tid  = threadIdx.x;
    const int tx   = tid & 15;        // 0..15 -> 4 cols each
    const int ty   = tid >> 4;        // 0..15 -> 8 rows each
    const int aRow = tid >> 1;        // 0..127
    const int aH   = tid & 1;         // which 8-k half
    const int bRow = tid >> 4;        // 0..15
    const int bC4  = tid & 15;        // 0..15

    const int rowBase = blockIdx.y * 128;
    const int colBase = blockIdx.x * 64;

    u64 acc2[4][4];                   // [rowpair][col]
    #pragma unroll
    for (int p = 0; p < 4; p++)
        #pragma unroll
        for (int c = 0; c < 4; c++) acc2[p][c] = 0ull;

    for (int k0 = 0; k0 < K; k0 += 16) {
        // A tile: 128 rows x 16 k. Each thread: 2 float4 (8 k) at half aH.
        {
            const float* arow = A + (size_t)(rowBase + aRow) * K + k0 + aH * 8;
            const float4 a0 = *(const float4*)(arow);
            const float4 a1 = *(const float4*)(arow + 4);
            const int kb = aH * 8;
            As[kb + 0][aRow] = a0.x; As[kb + 1][aRow] = a0.y;
            As[kb + 2][aRow] = a0.z; As[kb + 3][aRow] = a0.w;
            As[kb + 4][aRow] = a1.x; As[kb + 5][aRow] = a1.y;
            As[kb + 6][aRow] = a1.z; As[kb + 7][aRow] = a1.w;
        }
        *(float4*)&Bs[bRow][bC4 * 4] =
            *(const float4*)(W + (size_t)(k0 + bRow) * Nc + colBase + bC4 * 4);
        __syncthreads();

        #pragma unroll
        for (int kk = 0; kk < 16; kk++) {
            const ulonglong2 ap0 = *(const ulonglong2*)&As[kk][ty * 8];
            const ulonglong2 ap1 = *(const ulonglong2*)&As[kk][ty * 8 + 4];
            const float4 bv = *(const float4*)&Bs[kk][tx * 4];
            const u64 b0 = pack2(bv.x, bv.x);
            const u64 b1 = pack2(bv.y, bv.y);
            const u64 b2 = pack2(bv.z, bv.z);
            const u64 b3 = pack2(bv.w, bv.w);
            const u64 ap[4] = {ap0.x, ap0.y, ap1.x, ap1.y};
            #pragma unroll
            for (int p = 0; p < 4; p++) {
                acc2[p][0] = fma2(ap[p], b0, acc2[p][0]);
                acc2[p][1] = fma2(ap[p], b1, acc2[p][1]);
                acc2[p][2] = fma2(ap[p], b2, acc2[p][2]);
                acc2[p][3] = fma2(ap[p], b3, acc2[p][3]);
            }
        }
        __syncthreads();
    }

    // epilogue: thread owns rows rowBase+ty*8+2p+{0,1}, cols colBase+tx*4..+3
    #pragma unroll
    for (int p = 0; p < 4; p++) {
        float r0v[4], r1v[4];
        #pragma unroll
        for (int c = 0; c < 4; c++) unpack2(acc2[p][c], r0v[c], r1v[c]);
        #pragma unroll
        for (int half = 0; half < 2; half++) {
            const int row = rowBase + ty * 8 + 2 * p + half;
            float* vv = half ? r1v : r0v;
            bool zero = false;
            if (lengths) zero = ((row & 2047) >= lengths[row >> 11]);
            const int col = colBase + tx * 4;
            float o0 = vv[0], o1 = vv[1], o2 = vv[2], o3 = vv[3];
            if (bias) {
                o0 += bias[col];     o1 += bias[col + 1];
                o2 += bias[col + 2]; o3 += bias[col + 3];
            }
            if (res) {
                const float4 rr = *(const float4*)(res + (size_t)row * Cld + col);
                o0 += rr.x; o1 += rr.y; o2 += rr.z; o3 += rr.w;
            }
            if (zero) { o0 = o1 = o2 = o3 = 0.0f; }
            *(float4*)(C + (size_t)row * Cld + colOff + col) = make_float4(o0, o1, o2, o3);
        }
    }
}

// ---------------------------------------------------------------------------
// HMMA bf16x3 GEMM, in-kernel truncation hi/lo split [R8/R10-validated VERBATIM]
// ---------------------------------------------------------------------------
#define T_AHI 0
#define T_ALO 10240
#define T_BHI 20480
#define T_BLO 30720
#define STG_OFF 40960
#define STG_SZ  32768
#define GSMEMT (STG_OFF + 2 * STG_SZ)

__global__ __launch_bounds__(256, 2)
void gemm_mma32(const float* __restrict__ A, const float* __restrict__ B,
                const float* __restrict__ bias, const float* __restrict__ res,
                float* __restrict__ C, int M, int Nc, int K,
                int Cld, int colOff, const int* __restrict__ lengths)
{
    extern __shared__ __align__(1024) char smem_raw[];
    const uint32_t sb = smem_u32(smem_raw);
    const int tid = threadIdx.x;
    const int wid = tid >> 5, l = tid & 31;
    const int wm = (wid >> 2) * 64;
    const int wn = (wid & 3) * 32;
    const int g  = l >> 2;
    const int qd = (l & 3) * 2;

    const int rowBase = blockIdx.y * 128;
    const int colBase = blockIdx.x * 128;

    const int seg = tid & 7;
    const int rb  = tid >> 3;

    float acc[4][4][4];
    #pragma unroll
    for (int a = 0; a < 4; a++)
        #pragma unroll
        for (int b = 0; b < 4; b++)
            #pragma unroll
            for (int c = 0; c < 4; c++) acc[a][b][c] = 0.0f;

    const int nch = K >> 5;

    #pragma unroll
    for (int it = 0; it < 8; it++) {
        const int grow = rb + it * 32;
        const float* src = (it < 4) ? (A + (size_t)(rowBase + grow) * K)
                                    : (B + (size_t)(colBase + grow - 128) * K);
        cpa16(sb + STG_OFF + (uint32_t)(grow * 128 + seg * 16), src + seg * 4);
    }
    CP_COMMIT();

    for (int ck = 0; ck < nch; ck++) {
        if (ck + 1 < nch) {
            const int kb = (ck + 1) * 32;
            const uint32_t ds = sb + STG_OFF + (uint32_t)(((ck + 1) & 1) * STG_SZ);
            #pragma unroll
            for (int it = 0; it < 8; it++) {
                const int grow = rb + it * 32;
                const float* src = (it < 4) ? (A + (size_t)(rowBase + grow) * K)
                                            : (B + (size_t)(colBase + grow - 128) * K);
                cpa16(ds + (uint32_t)(grow * 128 + seg * 16), src + kb + seg * 4);
            }
            CP_COMMIT();
            CP_WAIT(1);
        } else {
            CP_WAIT(0);
        }
        __syncthreads();

        {
            const char* sp = smem_raw + STG_OFF + (size_t)(ck & 1) * STG_SZ;
            #pragma unroll
            for (int it = 0; it < 8; it++) {
                const int grow = rb + it * 32;
                const float4 v = *(const float4*)(sp + grow * 128 + seg * 16);
                const uint32_t u0 = __float_as_uint(v.x), u1 = __float_as_uint(v.y);
                const uint32_t u2 = __float_as_uint(v.z), u3 = __float_as_uint(v.w);
                const uint32_t hi0 = (u0 >> 16) | (u1 & 0xFFFF0000u);
                const uint32_t hi1 = (u2 >> 16) | (u3 & 0xFFFF0000u);
                const float l0 = v.x - __uint_as_float(u0 & 0xFFFF0000u);
                const float l1 = v.y - __uint_as_float(u1 & 0xFFFF0000u);
                const float l2 = v.z - __uint_as_float(u2 & 0xFFFF0000u);
                const float l3 = v.w - __uint_as_float(u3 & 0xFFFF0000u);
                __nv_bfloat162 lp0 = __floats2bfloat162_rn(l0, l1);
                __nv_bfloat162 lp1 = __floats2bfloat162_rn(l2, l3);
                const uint32_t lo0 = *reinterpret_cast<uint32_t*>(&lp0);
                const uint32_t lo1 = *reinterpret_cast<uint32_t*>(&lp1);
                const int tr = grow & 127;
                char* hb = smem_raw + ((it < 4) ? T_AHI : T_BHI) + tr * 80 + seg * 8;
                char* lb = smem_raw + ((it < 4) ? T_ALO : T_BLO) + tr * 80 + seg * 8;
                *(uint2*)hb = make_uint2(hi0, hi1);
                *(uint2*)lb = make_uint2(lo0, lo1);
            }
        }
        __syncthreads();

        #pragma unroll
        for (int s = 0; s < 32; s += 16) {
            const int c0 = (s + qd) * 2;
            const int c1 = (s + qd + 8) * 2;
            uint32_t a[4][4], bh[4][2], bl[4][2];

            #pragma unroll
            for (int nt = 0; nt < 4; nt++) {
                const int ro = (wn + nt * 8 + g) * 80;
                bh[nt][0] = *(const uint32_t*)(smem_raw + T_BHI + ro + c0);
                bh[nt][1] = *(const uint32_t*)(smem_raw + T_BHI + ro + c1);
                bl[nt][0] = *(const uint32_t*)(smem_raw + T_BLO + ro + c0);
                bl[nt][1] = *(const uint32_t*)(smem_raw + T_BLO + ro + c1);
            }
            #pragma unroll
            for (int mt = 0; mt < 4; mt++) {
                const int r0 = (wm + mt * 16 + g) * 80;
                const int r1 = r0 + 8 * 80;
                a[mt][0] = *(const uint32_t*)(smem_raw + T_AHI + r0 + c0);
                a[mt][1] = *(const uint32_t*)(smem_raw + T_AHI + r1 + c0);
                a[mt][2] = *(const uint32_t*)(smem_raw + T_AHI + r0 + c1);
                a[mt][3] = *(const uint32_t*)(smem_raw + T_AHI + r1 + c1);
            }
            #pragma unroll
            for (int mt = 0; mt < 4; mt++)
                #pragma unroll
                for (int nt = 0; nt < 4; nt++)
                    mma_bf16(acc[mt][nt], a[mt], bh[nt]);   // Ahi*Bhi
            #pragma unroll
            for (int mt = 0; mt < 4; mt++)
                #pragma unroll
                for (int nt = 0; nt < 4; nt++)
                    mma_bf16(acc[mt][nt], a[mt], bl[nt]);   // Ahi*Blo
            #pragma unroll
            for (int mt = 0; mt < 4; mt++) {
                const int r0 = (wm + mt * 16 + g) * 80;
                const int r1 = r0 + 8 * 80;
                a[mt][0] = *(const uint32_t*)(smem_raw + T_ALO + r0 + c0);
                a[mt][1] = *(const uint32_t*)(smem_raw + T_ALO + r1 + c0);
                a[mt][2] = *(const uint32_t*)(smem_raw + T_ALO + r0 + c1);
                a[mt][3] = *(const uint32_t*)(smem_raw + T_ALO + r1 + c1);
            }
            #pragma unroll
            for (int mt = 0; mt < 4; mt++)
                #pragma unroll
                for (int nt = 0; nt < 4; nt++)
                    mma_bf16(acc[mt][nt], a[mt], bh[nt]);   // Alo*Bhi
        }
    }

    #pragma unroll
    for (int mt = 0; mt < 4; mt++) {
        #pragma unroll
        for (int hrow = 0; hrow < 2; hrow++) {
            const int row = rowBase + wm + mt * 16 + g + hrow * 8;
            bool zero = false;
            if (lengths) zero = ((row & 2047) >= lengths[row >> 11]);
            #pragma unroll
            for (int nt = 0; nt < 4; nt++) {
                const int col = colBase + wn + nt * 8 + qd;
                float v0 = acc[mt][nt][hrow * 2 + 0];
                float v1 = acc[mt][nt][hrow * 2 + 1];
                if (bias) { v0 += bias[col]; v1 += bias[col + 1]; }
                if (res) {
                    const float2 rr = *(const float2*)(res + (size_t)row * Cld + colOff + col);
                    v0 += rr.x; v1 += rr.y;
                }
                if (zero) { v0 = 0.0f; v1 = 0.0f; }
                *(float2*)(C + (size_t)row * Cld + colOff + col) = make_float2(v0, v1);
            }
        }
    }
}

// ---------------------------------------------------------------------------
// Flash attention v2: 256 threads/block (256 queries share K/V tiles),
// ILP-2 over keys. f32x2 arithmetic. Proven control-flow semantics.
// ---------------------------------------------------------------------------
__global__ __launch_bounds__(256)
void attn_kernel(const float* __restrict__ Q, int qStr,
                 const float* __restrict__ KV, int kvStr, int kOff, int vOff,
                 const int* __restrict__ lengths,
                 float* __restrict__ O, int kv_len)
{
    const int b = blockIdx.z;
    const int h = blockIdx.y;
    const int qrow = b * CN + blockIdx.x * 256 + threadIdx.x;

    u64 q2r[32];
    {
        const float4* qp = (const float4*)(Q + (size_t)qrow * qStr + h * CDH);
        #pragma unroll
        for (int d4 = 0; d4 < 16; d4++) {
            float4 t4 = qp[d4];
            q2r[2*d4]   = pack2(t4.x * 0.125f, t4.y * 0.125f);
            q2r[2*d4+1] = pack2(t4.z * 0.125f, t4.w * 0.125f);
        }
    }

    float m = -1e30f, l = 0.0f;
    u64 acc2[32];
    #pragma unroll
    for (int d = 0; d < 32; d++) acc2[d] = 0ull;

    const int valid = lengths ? lengths[b] : kv_len;
    const size_t kvBase = (size_t)b * kv_len;

    __shared__ __align__(16) float Ks[64][64];
    __shared__ __align__(16) float Vs[64][64];

    for (int t0 = 0; t0 < valid; t0 += 64) {
        const int tcount = min(64, valid - t0);
        for (int i = threadIdx.x; i < 64 * 16; i += 256) {
            const int r  = i >> 4;
            const int c4 = i & 15;
            const size_t base = (kvBase + t0 + r) * kvStr + h * CDH + c4 * 4;
            ((float4*)Ks[r])[c4] = *(const float4*)(KV + base + kOff);
            ((float4*)Vs[r])[c4] = *(const float4*)(KV + base + vOff);
        }
        __syncthreads();

        int j = 0;
        for (; j + 1 < tcount; j += 2) {
            const ulonglong2* kr0 = (const ulonglong2*)Ks[j];
            const ulonglong2* kr1 = (const ulonglong2*)Ks[j + 1];
            u64 a0 = 0ull, a1 = 0ull, c0 = 0ull, c1 = 0ull;
            #pragma unroll
            for (int i = 0; i < 16; i++) {
                const ulonglong2 kA = kr0[i];
                const ulonglong2 kB = kr1[i];
                a0 = fma2(q2r[2*i],   kA.x, a0);
                a1 = fma2(q2r[2*i+1], kA.y, a1);
                c0 = fma2(q2r[2*i],   kB.x, c0);
                c1 = fma2(q2r[2*i+1], kB.y, c1);
            }
            float s0a, s0b, s1a, s1b;
            unpack2(add2(a0, a1), s0a, s0b);
            unpack2(add2(c0, c1), s1a, s1b);
            const float s0 = s0a + s0b;
            const float s1 = s1a + s1b;

            const float mn = fmaxf(m, fmaxf(s0, s1));
            if (mn > m) {
                const float cc = __expf(m - mn);
                const u64 cc2 = pack2(cc, cc);
                l *= cc;
                #pragma unroll
                for (int d = 0; d < 32; d++) acc2[d] = mul2(acc2[d], cc2);
                m = mn;
            }
            const float p0 = __expf(s0 - m);
            const float p1 = __expf(s1 - m);
            l += p0 + p1;
            const u64 P0 = pack2(p0, p0);
            const u64 P1 = pack2(p1, p1);
            const ulonglong2* vr0 = (const ulonglong2*)Vs[j];
            const ulonglong2* vr1 = (const ulonglong2*)Vs[j + 1];
            #pragma unroll
            for (int i = 0; i < 16; i++) {
                const ulonglong2 v0 = vr0[i];
                const ulonglong2 v1 = vr1[i];
                acc2[2*i]   = fma2(P0, v0.x, acc2[2*i]);
                acc2[2*i+1] = fma2(P0, v0.y, acc2[2*i+1]);
                acc2[2*i]   = fma2(P1, v1.x, acc2[2*i]);
                acc2[2*i+1] = fma2(P1, v1.y, acc2[2*i+1]);
            }
        }
        if (j < tcount) {   // tail single key
            const ulonglong2* kr = (const ulonglong2*)Ks[j];
            u64 p0 = 0ull, p1 = 0ull;
            #pragma unroll
            for (int i = 0; i < 16; i++) {
                const ulonglong2 k0 = kr[i];
                p0 = fma2(q2r[2*i],   k0.x, p0);
                p1 = fma2(q2r[2*i+1], k0.y, p1);
            }
            float sa, sb2;
            unpack2(add2(p0, p1), sa, sb2);
            const float s = sa + sb2;
            if (s > m) {
                const float cc = __expf(m - s);
                const u64 cc2 = pack2(cc, cc);
                l *= cc;
                #pragma unroll
                for (int d = 0; d < 32; d++) acc2[d] = mul2(acc2[d], cc2);
                m = s;
            }
            const float pr = __expf(s - m);
            l += pr;
            const u64 pr2 = pack2(pr, pr);
            const ulonglong2* vr = (const ulonglong2*)Vs[j];
            #pragma unroll
            for (int i = 0; i < 16; i++) {
                const ulonglong2 v = vr[i];
                acc2[2*i]   = fma2(pr2, v.x, acc2[2*i]);
                acc2[2*i+1] = fma2(pr2, v.y, acc2[2*i+1]);
            }
        }
        __syncthreads();
    }

    const float inv = 1.0f / l;
    float4* op = (float4*)(O + (size_t)qrow * CINNER + h * CDH);
    #pragma unroll
    for (int d4 = 0; d4 < 16; d4++) {
        float o0, o1, o2, o3;
        unpack2(acc2[2*d4],   o0, o1);
        unpack2(acc2[2*d4+1], o2, o3);
        float4 o;
        o.x = o0 * inv; o.y = o1 * inv; o.z = o2 * inv; o.w = o3 * inv;
        op[d4] = o;
    }
}

// ---------------------------------------------------------------------------
// GEGLU (fp32, proven)
// ---------------------------------------------------------------------------
__global__ __launch_bounds__(256)
void geglu_kernel(const float* __restrict__ p, float* __restrict__ out)
{
    const size_t i = (size_t)blockIdx.x * 256 + threadIdx.x;
    const size_t row = i >> 11;
    const size_t col = i & 2047;
    const float a = p[row * 4096 + col];
    const float gt = p[row * 4096 + 2048 + col];
    const float gelu = 0.5f * gt * (1.0f + erff(gt * 0.70710678118654752f));
    out[i] = a * gelu;
}

// ---------------------------------------------------------------------------
// Launch (R8/R10-passing structure)
// ---------------------------------------------------------------------------
extern "C" void kernel_launch(void* const* d_in, const int* in_sizes, int n_in,
                              void* d_out, int out_size)
{
    (void)in_sizes; (void)n_in; (void)out_size;
    const float* x      = (const float*)d_in[0];
    const float* ctx    = (const float*)d_in[1];
    const int*   len    = (const int*)  d_in[2];
    const float* wq1    = (const float*)d_in[3];
    const float* wk1    = (const float*)d_in[4];
    const float* wv1    = (const float*)d_in[5];
    const float* wo1    = (const float*)d_in[6];
    const float* bo1    = (const float*)d_in[7];
    const float* wq2    = (const float*)d_in[8];
    const float* wk2    = (const float*)d_in[9];
    const float* wv2    = (const float*)d_in[10];
    const float* wo2    = (const float*)d_in[11];
    const float* bo2    = (const float*)d_in[12];
    const float* wff_in = (const float*)d_in[13];
    const float* bff_in = (const float*)d_in[14];
    const float* wff_out= (const float*)d_in[15];
    const float* bff_out= (const float*)d_in[16];
    const float* g1     = (const float*)d_in[17];
    const float* b1     = (const float*)d_in[18];
    const float* g2     = (const float*)d_in[19];
    const float* b2     = (const float*)d_in[20];
    const float* g3     = (const float*)d_in[21];
    const float* b3     = (const float*)d_in[22];
    float* out = (float*)d_out;

    cudaFuncSetAttribute(gemm_mma32, cudaFuncAttributeMaxDynamicSharedMemorySize, GSMEMT);

    float *h, *att, *gg, *qkv, *q2, *ckv, *x1, *x2, *p;
    float *wq1t, *wk1t, *wv1t, *wq2t, *wk2t, *wv2t, *wfit;
    cudaGetSymbolAddress((void**)&h,   g_h);
    cudaGetSymbolAddress((void**)&att, g_att);
    cudaGetSymbolAddress((void**)&gg,  g_gg);
    cudaGetSymbolAddress((void**)&qkv, g_qkv);
    cudaGetSymbolAddress((void**)&q2,  g_q2);
    cudaGetSymbolAddress((void**)&ckv, g_ckv);
    cudaGetSymbolAddress((void**)&x1,  g_x1);
    cudaGetSymbolAddress((void**)&x2,  g_x2);
    cudaGetSymbolAddress((void**)&p,   g_p);
    cudaGetSymbolAddress((void**)&wq1t, g_wq1t);
    cudaGetSymbolAddress((void**)&wk1t, g_wk1t);
    cudaGetSymbolAddress((void**)&wv1t, g_wv1t);
    cudaGetSymbolAddress((void**)&wq2t, g_wq2t);
    cudaGetSymbolAddress((void**)&wk2t, g_wk2t);
    cudaGetSymbolAddress((void**)&wv2t, g_wv2t);
    cudaGetSymbolAddress((void**)&wfit, g_wfit);

    const dim3 tb(32, 8);
    transp32<<<dim3(16, 16), tb>>>(wq1, 512, 512, wq1t);
    transp32<<<dim3(16, 16), tb>>>(wk1, 512, 512, wk1t);
    transp32<<<dim3(16, 16), tb>>>(wv1, 512, 512, wv1t);
    transp32<<<dim3(16, 16), tb>>>(wq2, 512, 512, wq2t);
    transp32<<<dim3(16, 24), tb>>>(wk2, 768, 512, wk2t);
    transp32<<<dim3(16, 24), tb>>>(wv2, 768, 512, wv2t);
    transp32<<<dim3(128, 16), tb>>>(wff_in, 512, 4096, wfit);

    const dim3 mP(4, 128);    // MMA: Nc=512,  M=16384
    const dim3 mC(4, 16);     // MMA: Nc=512,  M=2048
    const dim3 mF(32, 128);   // MMA: Nc=4096, M=16384
    const dim3 gP(8, 128);    // gemm32 v2: Nc=512 (8 col-blocks), M=16384 (128 row-blocks)
    const dim3 gA(CN/256, CH, CB);  // attention: 256 queries/block

    // ---- Phase 1: self-attention ----
    ln_kernel<<<CBN, 128>>>(x, g1, b1, h);
    gemm_mma32<<<mP, 256, GSMEMT>>>(h, wq1t, nullptr, nullptr, qkv, CBN, 512, 512, 1536, 0,    nullptr);
    gemm_mma32<<<mP, 256, GSMEMT>>>(h, wk1t, nullptr, nullptr, qkv, CBN, 512, 512, 1536, 512,  nullptr);
    gemm_mma32<<<mP, 256, GSMEMT>>>(h, wv1t, nullptr, nullptr, qkv, CBN, 512, 512, 1536, 1024, nullptr);
    attn_kernel<<<gA, 256>>>(qkv, 1536, qkv, 1536, 512, 1024, len, att, CN);
    gemm32<<<gP, 256>>>(att, wo1, bo1, x, x1, CBN, 512, 512, 512, 0, nullptr);

    // ---- Phase 2: cross-attention ----
    ln_kernel<<<CBN, 128>>>(x1, g2, b2, h);
    gemm_mma32<<<mP, 256, GSMEMT>>>(h, wq2t, nullptr, nullptr, q2, CBN, 512, 512, 512, 0, nullptr);
    gemm_mma32<<<mC, 256, GSMEMT>>>(ctx, wk2t, nullptr, nullptr, ckv, CBS, 512, 768, 1024, 0,   nullptr);
    gemm_mma32<<<mC, 256, GSMEMT>>>(ctx, wv2t, nullptr, nullptr, ckv, CBS, 512, 768, 1024, 512, nullptr);
    attn_kernel<<<gA, 256>>>(q2, 512, ckv, 1024, 0, 512, nullptr, att, CS);
    gemm32<<<gP, 256>>>(att, wo2, bo2, x1, x2, CBN, 512, 512, 512, 0, nullptr);

    // ---- Phase 3: GEGLU feed-forward ----
    ln_kernel<<<CBN, 128>>>(x2, g3, b3, h);
    gemm_mma32<<<mF, 256, GSMEMT>>>(h, wfit, bff_in, nullptr, p, CBN, 4096, 512, 4096, 0, nullptr);
    geglu_kernel<<<((size_t)CBN * CFF) / 256, 256>>>(p, gg);
    gemm32<<<gP, 256>>>(gg, wff_out, bff_out, x2, out, CBN, 512, 2048, 512, 0, len);
}